// round 14
// baseline (speedup 1.0000x reference)
#include <cuda_runtime.h>
#include <cuda_fp16.h>
#include <math.h>
#include <stdint.h>

#define KB   2
#define KTQ  4096
#define KS   1024
#define KD   256
#define KH   8
#define KL   4
#define KP   2047
#define XE   (KB*KTQ*KD)

__device__ float g_scratch[12057344];
__device__ __half g_ews[67108864];

// ===================== mma.sync fp16 m16n8k16 ========================
__device__ __forceinline__ void mma_f16(float* c, const uint32_t* a, const uint32_t* b) {
    asm volatile("mma.sync.aligned.m16n8k16.row.col.f32.f16.f16.f32 "
        "{%0,%1,%2,%3}, {%4,%5,%6,%7}, {%8,%9}, {%0,%1,%2,%3};\n"
        : "+f"(c[0]), "+f"(c[1]), "+f"(c[2]), "+f"(c[3])
        : "r"(a[0]), "r"(a[1]), "r"(a[2]), "r"(a[3]), "r"(b[0]), "r"(b[1]));
}
__device__ __forceinline__ uint2 f4_to_h4(float4 v) {
    __half2 h01 = __floats2half2_rn(v.x, v.y);
    __half2 h23 = __floats2half2_rn(v.z, v.w);
    uint2 u;
    u.x = *reinterpret_cast<uint32_t*>(&h01);
    u.y = *reinterpret_cast<uint32_t*>(&h23);
    return u;
}

// ============================ pe =================================
__global__ void pe_kernel(float* __restrict__ pe) {
    int i = blockIdx.x;
    int j = threadIdx.x;
    double div = exp(-(double)j * 9.210340371976184 / 128.0);
    double a = (1023.0 - (double)i) * div;
    pe[i * KD + 2 * j]     = (float)sin(a);
    pe[i * KD + 2 * j + 1] = (float)cos(a);
}

// ============ proj via fp16 big/small split (3 x m16n8k16), 512 thr =========
#define PHSTR 40
#define PH_AB 0
#define PH_AS 5120
#define PH_WB 10240
#define PH_WS 15360
#define PJ_SMEM 40960

__global__ __launch_bounds__(512) void proj_mma(
    const float* __restrict__ A, const float* __restrict__ W,
    const float* __restrict__ bias, float* __restrict__ C,
    int M, int wStride, int cStride,
    const float* __restrict__ W2, const float* __restrict__ bias2,
    float* __restrict__ C2, int zSplit)
{
    extern __shared__ float sp[];
    __half* sph = (__half*)sp;
    int m0 = blockIdx.x * 128, n0 = blockIdx.y * 128;
    int z = blockIdx.z;
    if (z >= zSplit) { W = W2; bias = bias2; C = C2; z -= zSplit; }
    W += (long long)z * wStride;
    C += (long long)z * cStride;
    if (bias) bias += z * 256;
    int tid = threadIdx.x;
    int wid = tid >> 5, lane = tid & 31;
    int wy = wid >> 2, wx = wid & 3;
    int g = lane >> 2, t = lane & 3;
    float acc[2][4][4] = {};

    for (int k0 = 0; k0 < 256; k0 += 32) {
        #pragma unroll
        for (int it = 0; it < 2; it++) {
            int e = tid + 512 * it;
            int r = e >> 3, f = e & 7;
            int row = m0 + r;
            float4 a4 = (row < M) ? *(const float4*)&A[(long long)row * 256 + k0 + f * 4]
                                  : make_float4(0.f, 0.f, 0.f, 0.f);
            uint2 ah = f4_to_h4(a4);
            float2 af01 = __half22float2(*reinterpret_cast<__half2*>(&ah.x));
            float2 af23 = __half22float2(*reinterpret_cast<__half2*>(&ah.y));
            uint2 al = f4_to_h4(make_float4(a4.x - af01.x, a4.y - af01.y,
                                            a4.z - af23.x, a4.w - af23.y));
            *(uint2*)&sph[PH_AB + r * PHSTR + f * 4] = ah;
            *(uint2*)&sph[PH_AS + r * PHSTR + f * 4] = al;
            float4 w4 = *(const float4*)&W[(long long)(n0 + r) * 256 + k0 + f * 4];
            uint2 wh = f4_to_h4(w4);
            float2 wf01 = __half22float2(*reinterpret_cast<__half2*>(&wh.x));
            float2 wf23 = __half22float2(*reinterpret_cast<__half2*>(&wh.y));
            uint2 wl = f4_to_h4(make_float4(w4.x - wf01.x, w4.y - wf01.y,
                                            w4.z - wf23.x, w4.w - wf23.y));
            *(uint2*)&sph[PH_WB + r * PHSTR + f * 4] = wh;
            *(uint2*)&sph[PH_WS + r * PHSTR + f * 4] = wl;
        }
        __syncthreads();
        #pragma unroll
        for (int k0i = 0; k0i < 2; k0i++) {
            int kk = k0i * 16;
            uint32_t aB[2][4], aS[2][4], bB[4][2], bS[4][2];
            #pragma unroll
            for (int mi = 0; mi < 2; mi++) {
                int r0 = wy * 32 + mi * 16;
                aB[mi][0] = *(const uint32_t*)&sph[PH_AB + (r0 + g) * PHSTR + kk + 2 * t];
                aB[mi][1] = *(const uint32_t*)&sph[PH_AB + (r0 + g + 8) * PHSTR + kk + 2 * t];
                aB[mi][2] = *(const uint32_t*)&sph[PH_AB + (r0 + g) * PHSTR + kk + 2 * t + 8];
                aB[mi][3] = *(const uint32_t*)&sph[PH_AB + (r0 + g + 8) * PHSTR + kk + 2 * t + 8];
                aS[mi][0] = *(const uint32_t*)&sph[PH_AS + (r0 + g) * PHSTR + kk + 2 * t];
                aS[mi][1] = *(const uint32_t*)&sph[PH_AS + (r0 + g + 8) * PHSTR + kk + 2 * t];
                aS[mi][2] = *(const uint32_t*)&sph[PH_AS + (r0 + g) * PHSTR + kk + 2 * t + 8];
                aS[mi][3] = *(const uint32_t*)&sph[PH_AS + (r0 + g + 8) * PHSTR + kk + 2 * t + 8];
            }
            #pragma unroll
            for (int ni = 0; ni < 4; ni++) {
                int c0 = wx * 32 + ni * 8;
                bB[ni][0] = *(const uint32_t*)&sph[PH_WB + (c0 + g) * PHSTR + kk + 2 * t];
                bB[ni][1] = *(const uint32_t*)&sph[PH_WB + (c0 + g) * PHSTR + kk + 2 * t + 8];
                bS[ni][0] = *(const uint32_t*)&sph[PH_WS + (c0 + g) * PHSTR + kk + 2 * t];
                bS[ni][1] = *(const uint32_t*)&sph[PH_WS + (c0 + g) * PHSTR + kk + 2 * t + 8];
            }
            #pragma unroll
            for (int mi = 0; mi < 2; mi++)
                #pragma unroll
                for (int ni = 0; ni < 4; ni++) {
                    mma_f16(acc[mi][ni], aB[mi], bS[ni]);
                    mma_f16(acc[mi][ni], aS[mi], bB[ni]);
                    mma_f16(acc[mi][ni], aB[mi], bB[ni]);
                }
        }
        __syncthreads();
    }
    #pragma unroll
    for (int mi = 0; mi < 2; mi++) {
        int r1 = m0 + wy * 32 + mi * 16 + g;
        int r2 = r1 + 8;
        #pragma unroll
        for (int ni = 0; ni < 4; ni++) {
            int cx = wx * 32 + ni * 8 + 2 * t;
            float b0 = bias ? bias[n0 + cx] : 0.f;
            float b1 = bias ? bias[n0 + cx + 1] : 0.f;
            if (r1 < M)
                *(float2*)&C[(long long)r1 * 256 + n0 + cx] =
                    make_float2(acc[mi][ni][0] + b0, acc[mi][ni][1] + b1);
            if (r2 < M)
                *(float2*)&C[(long long)r2 * 256 + n0 + cx] =
                    make_float2(acc[mi][ni][2] + b0, acc[mi][ni][3] + b1);
        }
    }
}

// ===== scores: fp16 MMA, unbiased Q + bias-dot vectors, fp16 G, 2 CTA/SM ====
#define HSTR 40
#define QH_O  0
#define KTH_O 5240
#define PDH_O 10360
#define GH_O  20608
#define GH_STR 258
// float indices (halves end at 53632 -> float index 26816)
#define BK_O 26816
#define BP_O 26944
#define SMAX_O 27200
#define SSUM_O 27712
#define SC_SMEM (28224 * 4)

__global__ __launch_bounds__(256, 2) void scores_mma_kernel(
    const float* __restrict__ q, const float* __restrict__ kmat,
    const float* __restrict__ p, const float* __restrict__ pbu,
    const float* __restrict__ pbv, __half* __restrict__ ews,
    float2* __restrict__ gstats)
{
    extern __shared__ float sm[];
    __half* smh = (__half*)sm;
    int q0 = blockIdx.x * 128, m0 = blockIdx.y * 128;
    int bh = blockIdx.z;
    int b = bh >> 3, h = bh & 7;
    int tid = threadIdx.x;
    int wid = tid >> 5, lane = tid & 31;
    int wy = wid >> 2, wx = wid & 3;
    int g = lane >> 2, t = lane & 3;

    int dlo = m0 - q0 + 3969;
    int da  = dlo >> 11;
    bool boundary = ((dlo >> 11) != ((dlo + 254) >> 11));

    const float* qb = q + (long long)b * KTQ * 256 + h * 32;
    // stage Q rows [q0, q0+131) unbiased, fp16
    for (int e = tid; e < 131 * 8; e += 256) {
        int r = e >> 3, fj = e & 7;
        int rv = q0 + r; if (rv > KTQ - 1) rv = KTQ - 1;
        float4 a = *(const float4*)&qb[(long long)rv * 256 + fj * 4];
        *(uint2*)&smh[QH_O + r * HSTR + fj * 4] = f4_to_h4(a);
    }
    #pragma unroll
    for (int it = 0; it < 4; it++) {
        int e = tid + 256 * it;
        int r = e >> 3, fj = e & 7;
        float4 kk4 = *(const float4*)&kmat[(long long)(m0 + r) * 256 + h * 32 + fj * 4];
        *(uint2*)&smh[KTH_O + r * HSTR + fj * 4] = f4_to_h4(kk4);
    }
    #pragma unroll
    for (int it = 0; it < 8; it++) {
        int e = tid + 256 * it;
        int r = e >> 3, fj = e & 7;
        int d = dlo + r;
        int cm = d & 2047;
        float4 v = make_float4(0.f, 0.f, 0.f, 0.f);
        if (cm > 0 && r < 255)
            v = *(const float4*)&p[(long long)(cm - 1) * 256 + h * 32 + fj * 4];
        *(uint2*)&smh[PDH_O + r * HSTR + fj * 4] = f4_to_h4(v);
    }
    __syncthreads();

    // bias-dot vectors: buK[c] = bu.K[c] (c<128), bvP[j] = bv.Pd[j] (j<256)
    {
        float s = 0.f;
        #pragma unroll
        for (int k = 0; k < 32; k++)
            s += pbv[h * 32 + k] * __half2float(smh[PDH_O + tid * HSTR + k]);
        sm[BP_O + tid] = s;
        if (tid < 128) {
            float s2 = 0.f;
            #pragma unroll
            for (int k = 0; k < 32; k++)
                s2 += pbu[h * 32 + k] * __half2float(smh[KTH_O + tid * HSTR + k]);
            sm[BK_O + tid] = s2;
        }
    }

    // ---- phase 1: banded G[r][ix] = Q_sh[r] . Pd[ix], fp16 out ----
    if (!boundary) {
        int s0b = (wy == 0) ? 64 : 0;
        #pragma unroll
        for (int nh = 0; nh < 2; nh++) {
            float accg[4][3][4] = {};
            #pragma unroll
            for (int k0 = 0; k0 < 2; k0++) {
                int kk = k0 * 16;
                uint32_t a[4][4], bb[3][2];
                #pragma unroll
                for (int mi = 0; mi < 4; mi++) {
                    int r0 = wy * 64 + mi * 16 + da;
                    a[mi][0] = *(const uint32_t*)&smh[QH_O + (r0 + g) * HSTR + kk + 2 * t];
                    a[mi][1] = *(const uint32_t*)&smh[QH_O + (r0 + g + 8) * HSTR + kk + 2 * t];
                    a[mi][2] = *(const uint32_t*)&smh[QH_O + (r0 + g) * HSTR + kk + 2 * t + 8];
                    a[mi][3] = *(const uint32_t*)&smh[QH_O + (r0 + g + 8) * HSTR + kk + 2 * t + 8];
                }
                #pragma unroll
                for (int ni = 0; ni < 3; ni++) {
                    int c0 = s0b + (wx * 6 + nh * 3 + ni) * 8;
                    bb[ni][0] = *(const uint32_t*)&smh[PDH_O + (c0 + g) * HSTR + kk + 2 * t];
                    bb[ni][1] = *(const uint32_t*)&smh[PDH_O + (c0 + g) * HSTR + kk + 2 * t + 8];
                }
                #pragma unroll
                for (int mi = 0; mi < 4; mi++)
                    #pragma unroll
                    for (int ni = 0; ni < 3; ni++)
                        mma_f16(accg[mi][ni], a[mi], bb[ni]);
            }
            #pragma unroll
            for (int mi = 0; mi < 4; mi++) {
                int r1 = wy * 64 + mi * 16 + g;
                #pragma unroll
                for (int ni = 0; ni < 3; ni++) {
                    int cx = s0b + (wx * 6 + nh * 3 + ni) * 8 + 2 * t;
                    __half2 h0 = __floats2half2_rn(accg[mi][ni][0], accg[mi][ni][1]);
                    __half2 h1 = __floats2half2_rn(accg[mi][ni][2], accg[mi][ni][3]);
                    *(uint32_t*)&smh[GH_O + r1 * GH_STR + cx] =
                        *reinterpret_cast<uint32_t*>(&h0);
                    *(uint32_t*)&smh[GH_O + (r1 + 8) * GH_STR + cx] =
                        *reinterpret_cast<uint32_t*>(&h1);
                }
            }
        }
    } else {
        int trb = (tid >> 4) * 8, tcb = (tid & 15) * 8;
        #pragma unroll
        for (int i = 0; i < 8; i++) {
            int rr = trb + i;
            #pragma unroll
            for (int j = 0; j < 8; j++) {
                int c = tcb + j;
                int ix = c - rr + 127;
                int d = dlo + ix;
                int tt = rr + (d >> 11);
                float s = 0.f;
                #pragma unroll
                for (int k = 0; k < 32; k++)
                    s += __half2float(smh[QH_O + tt * HSTR + k])
                       * __half2float(smh[PDH_O + ix * HSTR + k]);
                smh[GH_O + rr * GH_STR + ix] = __float2half_rn(s);
            }
        }
    }
    __syncthreads();

    // ---- phase 2: ac = Q . K^T ----
    float acc[4][4][4] = {};
    #pragma unroll
    for (int k0 = 0; k0 < 2; k0++) {
        int kk = k0 * 16;
        uint32_t a[4][4], bb[4][2];
        #pragma unroll
        for (int mi = 0; mi < 4; mi++) {
            int r0 = wy * 64 + mi * 16;
            a[mi][0] = *(const uint32_t*)&smh[QH_O + (r0 + g) * HSTR + kk + 2 * t];
            a[mi][1] = *(const uint32_t*)&smh[QH_O + (r0 + g + 8) * HSTR + kk + 2 * t];
            a[mi][2] = *(const uint32_t*)&smh[QH_O + (r0 + g) * HSTR + kk + 2 * t + 8];
            a[mi][3] = *(const uint32_t*)&smh[QH_O + (r0 + g + 8) * HSTR + kk + 2 * t + 8];
        }
        #pragma unroll
        for (int ni = 0; ni < 4; ni++) {
            int c0 = wx * 32 + ni * 8;
            bb[ni][0] = *(const uint32_t*)&smh[KTH_O + (c0 + g) * HSTR + kk + 2 * t];
            bb[ni][1] = *(const uint32_t*)&smh[KTH_O + (c0 + g) * HSTR + kk + 2 * t + 8];
        }
        #pragma unroll
        for (int mi = 0; mi < 4; mi++)
            #pragma unroll
            for (int ni = 0; ni < 4; ni++)
                mma_f16(acc[mi][ni], a[mi], bb[ni]);
    }

    // ---- combine: v = (ac + buK + G + bvP) * sc ----
    const float sc = 0.17677669529663687f;
    #pragma unroll
    for (int mi = 0; mi < 4; mi++) {
        int r1 = wy * 64 + mi * 16 + g;
        int r2 = r1 + 8;
        #pragma unroll
        for (int ni = 0; ni < 4; ni++) {
            int cx = wx * 32 + ni * 8 + 2 * t;
            int i10 = cx - r1 + 127, i20 = cx - r2 + 127;
            acc[mi][ni][0] = (acc[mi][ni][0] + sm[BK_O + cx]
                + __half2float(smh[GH_O + r1 * GH_STR + i10]) + sm[BP_O + i10]) * sc;
            acc[mi][ni][1] = (acc[mi][ni][1] + sm[BK_O + cx + 1]
                + __half2float(smh[GH_O + r1 * GH_STR + i10 + 1]) + sm[BP_O + i10 + 1]) * sc;
            acc[mi][ni][2] = (acc[mi][ni][2] + sm[BK_O + cx]
                + __half2float(smh[GH_O + r2 * GH_STR + i20]) + sm[BP_O + i20]) * sc;
            acc[mi][ni][3] = (acc[mi][ni][3] + sm[BK_O + cx + 1]
                + __half2float(smh[GH_O + r2 * GH_STR + i20 + 1]) + sm[BP_O + i20 + 1]) * sc;
        }
    }

    // ---- row-tile max reduce ----
    __syncthreads();
    float rm1[4], rm2[4];
    #pragma unroll
    for (int mi = 0; mi < 4; mi++) {
        int lr1 = wy * 64 + mi * 16 + g;
        int lr2 = lr1 + 8;
        float mx1 = -1e30f, mx2 = -1e30f;
        #pragma unroll
        for (int ni = 0; ni < 4; ni++) {
            mx1 = fmaxf(mx1, fmaxf(acc[mi][ni][0], acc[mi][ni][1]));
            mx2 = fmaxf(mx2, fmaxf(acc[mi][ni][2], acc[mi][ni][3]));
        }
        mx1 = fmaxf(mx1, __shfl_xor_sync(0xffffffffu, mx1, 1));
        mx1 = fmaxf(mx1, __shfl_xor_sync(0xffffffffu, mx1, 2));
        mx2 = fmaxf(mx2, __shfl_xor_sync(0xffffffffu, mx2, 1));
        mx2 = fmaxf(mx2, __shfl_xor_sync(0xffffffffu, mx2, 2));
        if (t == 0) {
            sm[SMAX_O + lr1 * 4 + wx] = mx1;
            sm[SMAX_O + lr2 * 4 + wx] = mx2;
        }
    }
    __syncthreads();

    // ---- exp + store fp16 + sum reduce ----
    #pragma unroll
    for (int mi = 0; mi < 4; mi++) {
        int lr1 = wy * 64 + mi * 16 + g;
        int lr2 = lr1 + 8;
        float a1 = fmaxf(fmaxf(sm[SMAX_O + lr1 * 4], sm[SMAX_O + lr1 * 4 + 1]),
                         fmaxf(sm[SMAX_O + lr1 * 4 + 2], sm[SMAX_O + lr1 * 4 + 3]));
        float a2 = fmaxf(fmaxf(sm[SMAX_O + lr2 * 4], sm[SMAX_O + lr2 * 4 + 1]),
                         fmaxf(sm[SMAX_O + lr2 * 4 + 2], sm[SMAX_O + lr2 * 4 + 3]));
        rm1[mi] = a1; rm2[mi] = a2;
        long long grow1 = ((long long)bh * KTQ + q0 + lr1) * KS + m0;
        long long grow2 = grow1 + 8 * KS;
        float s1 = 0.f, s2 = 0.f;
        #pragma unroll
        for (int ni = 0; ni < 4; ni++) {
            int cx = wx * 32 + ni * 8 + 2 * t;
            float e0 = __expf(acc[mi][ni][0] - a1);
            float e1 = __expf(acc[mi][ni][1] - a1);
            float e2 = __expf(acc[mi][ni][2] - a2);
            float e3 = __expf(acc[mi][ni][3] - a2);
            s1 += e0 + e1;
            s2 += e2 + e3;
            *(__half2*)&ews[grow1 + cx] = __floats2half2_rn(e0, e1);
            *(__half2*)&ews[grow2 + cx] = __floats2half2_rn(e2, e3);
        }
        s1 += __shfl_xor_sync(0xffffffffu, s1, 1);
        s1 += __shfl_xor_sync(0xffffffffu, s1, 2);
        s2 += __shfl_xor_sync(0xffffffffu, s2, 1);
        s2 += __shfl_xor_sync(0xffffffffu, s2, 2);
        if (t == 0) {
            sm[SSUM_O + lr1 * 4 + wx] = s1;
            sm[SSUM_O + lr2 * 4 + wx] = s2;
        }
    }
    __syncthreads();
    if (wx == 0 && t == 0) {
        int my = m0 >> 7;
        long long sb = ((long long)bh * 8 + my) * KTQ + q0;
        #pragma unroll
        for (int mi = 0; mi < 4; mi++) {
            int lr1 = wy * 64 + mi * 16 + g;
            int lr2 = lr1 + 8;
            float s1 = sm[SSUM_O + lr1 * 4] + sm[SSUM_O + lr1 * 4 + 1]
                     + sm[SSUM_O + lr1 * 4 + 2] + sm[SSUM_O + lr1 * 4 + 3];
            float s2 = sm[SSUM_O + lr2 * 4] + sm[SSUM_O + lr2 * 4 + 1]
                     + sm[SSUM_O + lr2 * 4 + 2] + sm[SSUM_O + lr2 * 4 + 3];
            gstats[sb + lr1] = make_float2(rm1[mi], s1);
            gstats[sb + lr2] = make_float2(rm2[mi], s2);
        }
    }
}

// ===== av: raw fp16 e as A operand, fp16 V as B, fac folded in epilogue =====
#define AHSTR 72
#define AVH_A 0
#define AVH_V (128 * AHSTR)
#define AV_M 5760
#define AV_I 5888
#define AV_S 6016
#define AV_F 8064
#define AV_SMEM ((8064 + 1024) * 4)

__global__ __launch_bounds__(256) void av_fused(
    const __half* __restrict__ ews, float* __restrict__ ws,
    const float* __restrict__ vmat,
    const float2* __restrict__ gstats, float* __restrict__ ao)
{
    extern __shared__ float sv[];
    __half* svh = (__half*)sv;
    float2* sSt = (float2*)(sv + AV_S);
    int q0 = blockIdx.x * 128;
    int bh = blockIdx.y;
    int b = bh >> 3, h = bh & 7;
    int tid = threadIdx.x;
    int wid = tid >> 5, lane = tid & 31;
    int g = lane >> 2, t = lane & 3;

    for (int idx = tid; idx < 1024; idx += 256)
        sSt[idx] = gstats[(((long long)bh * 8 + (idx >> 7)) << 12) + q0 + (idx & 127)];
    __syncthreads();
    if (tid < 128) {
        float M = -1e30f;
        #pragma unroll
        for (int mt = 0; mt < 8; mt++) M = fmaxf(M, sSt[mt * 128 + tid].x);
        float s = 0.f;
        #pragma unroll
        for (int mt = 0; mt < 8; mt++)
            s += sSt[mt * 128 + tid].y * __expf(sSt[mt * 128 + tid].x - M);
        sv[AV_M + tid] = M;
        sv[AV_I + tid] = 1.f / s;
    }
    __syncthreads();
    for (int idx = tid; idx < 1024; idx += 256) {
        int r = idx & 127;
        sv[AV_F + idx] = __expf(sSt[idx].x - sv[AV_M + r]) * sv[AV_I + r];
    }
    __syncthreads();

    const __half* ewsrow = ews + ((long long)bh * KTQ + q0) * KS;
    float* wsrow = ws + ((long long)bh * KTQ + q0) * KS;
    float acc[4][4] = {};

    for (int s0 = 0; s0 < KS; s0 += 64) {
        int mt = s0 >> 7;
        #pragma unroll
        for (int it = 0; it < 4; it++) {
            int e = tid + 256 * it;
            int r = e >> 3, f = e & 7;
            long long off = (long long)r * KS + s0 + f * 8;
            uint4 rh = *(const uint4*)&ewsrow[off];
            *(uint4*)&svh[AVH_A + r * AHSTR + f * 8] = rh;
            float fac = sv[AV_F + mt * 128 + r];
            float2 p0 = __half22float2(*reinterpret_cast<__half2*>(&rh.x));
            float2 p1 = __half22float2(*reinterpret_cast<__half2*>(&rh.y));
            float2 p2 = __half22float2(*reinterpret_cast<__half2*>(&rh.z));
            float2 p3 = __half22float2(*reinterpret_cast<__half2*>(&rh.w));
            float4 o0 = make_float4(p0.x * fac, p0.y * fac, p1.x * fac, p1.y * fac);
            float4 o1 = make_float4(p2.x * fac, p2.y * fac, p3.x * fac, p3.y * fac);
            *(float4*)&wsrow[off]     = o0;
            *(float4*)&wsrow[off + 4] = o1;
        }
        #pragma unroll
        for (int it = 0; it < 8; it++) {
            int e = tid + 256 * it;
            int k = e >> 5, n = e & 31;
            svh[AVH_V + n * AHSTR + k] =
                __float2half_rn(vmat[(long long)(s0 + k) * 256 + h * 32 + n]);
        }
        __syncthreads();

        int r0 = wid * 16;
        float accC[4][4] = {};
        #pragma unroll
        for (int k0 = 0; k0 < 4; k0++) {
            int kk = k0 * 16;
            uint32_t a[4];
            a[0] = *(const uint32_t*)&svh[AVH_A + (r0 + g) * AHSTR + kk + 2 * t];
            a[1] = *(const uint32_t*)&svh[AVH_A + (r0 + g + 8) * AHSTR + kk + 2 * t];
            a[2] = *(const uint32_t*)&svh[AVH_A + (r0 + g) * AHSTR + kk + 2 * t + 8];
            a[3] = *(const uint32_t*)&svh[AVH_A + (r0 + g + 8) * AHSTR + kk + 2 * t + 8];
            #pragma unroll
            for (int ni = 0; ni < 4; ni++) {
                uint32_t bb[2];
                bb[0] = *(const uint32_t*)&svh[AVH_V + (ni * 8 + g) * AHSTR + kk + 2 * t];
                bb[1] = *(const uint32_t*)&svh[AVH_V + (ni * 8 + g) * AHSTR + kk + 2 * t + 8];
                mma_f16(accC[ni], a, bb);
            }
        }
        float facA = sv[AV_F + mt * 128 + r0 + g];
        float facB = sv[AV_F + mt * 128 + r0 + g + 8];
        #pragma unroll
        for (int ni = 0; ni < 4; ni++) {
            acc[ni][0] += facA * accC[ni][0];
            acc[ni][1] += facA * accC[ni][1];
            acc[ni][2] += facB * accC[ni][2];
            acc[ni][3] += facB * accC[ni][3];
        }
        __syncthreads();
    }
    int r1 = q0 + wid * 16 + g;
    float* aob = ao + ((long long)b * KTQ + r1) * 256 + h * 32;
    #pragma unroll
    for (int ni = 0; ni < 4; ni++) {
        int cx = ni * 8 + 2 * t;
        *(float2*)&aob[cx]           = make_float2(acc[ni][0], acc[ni][1]);
        *(float2*)&aob[8 * 256 + cx] = make_float2(acc[ni][2], acc[ni][3]);
    }
}

// ---------------------------------------------------------------------------
extern "C" void kernel_launch(void* const* d_in, const int* in_sizes, int n_in,
                              void* d_out, int out_size)
{
    const float* vis  = (const float*)d_in[0];
    const float* mem  = (const float*)d_in[1];
    const float* Wq   = (const float*)d_in[3];
    const float* bq   = (const float*)d_in[4];
    const float* Wk   = (const float*)d_in[5];
    const float* bk   = (const float*)d_in[6];
    const float* Wv   = (const float*)d_in[7];
    const float* bv   = (const float*)d_in[8];
    const float* Wo   = (const float*)d_in[9];
    const float* bo   = (const float*)d_in[10];
    const float* Wpos = (const float*)d_in[11];
    const float* pbu  = (const float*)d_in[12];
    const float* pbv  = (const float*)d_in[13];

    float* out    = (float*)d_out;
    float* out_ws = out + XE;

    float* scratch = nullptr;
    cudaGetSymbolAddress((void**)&scratch, g_scratch);
    __half* ews = nullptr;
    cudaGetSymbolAddress((void**)&ews, g_ews);
    float* pe = scratch;
    float* pp = pe + 524032;
    float* kk = pp + 4 * 524032;
    float* vv = kk + 4 * 262144;
    float* qq = vv + 4 * 262144;
    float* xx = qq + XE;
    float* ao = xx + XE;
    float2* gstats = (float2*)(ao + XE);

    cudaFuncSetAttribute(scores_mma_kernel,
        cudaFuncAttributeMaxDynamicSharedMemorySize, SC_SMEM);
    cudaFuncSetAttribute(proj_mma,
        cudaFuncAttributeMaxDynamicSharedMemorySize, PJ_SMEM);
    cudaFuncSetAttribute(av_fused,
        cudaFuncAttributeMaxDynamicSharedMemorySize, AV_SMEM);

    pe_kernel<<<KP, 128>>>(pe);

    proj_mma<<<dim3(8, 2, 2 * KL), 512, PJ_SMEM>>>(mem, Wk, bk, kk, KS, 65536, 262144,
                                                   Wv, bv, vv, KL);
    proj_mma<<<dim3(16, 2, KL), 512, PJ_SMEM>>>(pe, Wpos, nullptr, pp, KP, 65536, 524032,
                                                nullptr, nullptr, nullptr, 1 << 30);

    const float* cur = vis;
    for (int l = 0; l < KL; l++) {
        proj_mma<<<dim3(64, 2, 1), 512, PJ_SMEM>>>(cur, Wq + l * 65536, bq + l * 256,
                                                   qq, KB * KTQ, 0, 0,
                                                   nullptr, nullptr, nullptr, 1 << 30);
        float* wsl = out_ws + (long long)l * KB * KH * KTQ * KS;
        scores_mma_kernel<<<dim3(32, 8, 16), 256, SC_SMEM>>>(
            qq, kk + l * 262144, pp + l * 524032,
            pbu + l * 256, pbv + l * 256, ews, gstats);
        av_fused<<<dim3(32, 16), 256, AV_SMEM>>>(ews, wsl, vv + l * 262144, gstats, ao);
        float* nxt = (l == KL - 1) ? out : xx;
        proj_mma<<<dim3(64, 2, 1), 512, PJ_SMEM>>>(ao, Wo + l * 65536, bo + l * 256,
                                                   nxt, KB * KTQ, 0, 0,
                                                   nullptr, nullptr, nullptr, 1 << 30);
        cur = nxt;
    }
}

// round 15
// speedup vs baseline: 1.1431x; 1.1431x over previous
#include <cuda_runtime.h>
#include <cuda_fp16.h>
#include <math.h>
#include <stdint.h>

#define KB   2
#define KTQ  4096
#define KS   1024
#define KD   256
#define KH   8
#define KL   4
#define KP   2047
#define XE   (KB*KTQ*KD)

__device__ float g_scratch[12057344];
__device__ __half g_ews[67108864];

// ===================== mma.sync fp16 m16n8k16 ========================
__device__ __forceinline__ void mma_f16(float* c, const uint32_t* a, const uint32_t* b) {
    asm volatile("mma.sync.aligned.m16n8k16.row.col.f32.f16.f16.f32 "
        "{%0,%1,%2,%3}, {%4,%5,%6,%7}, {%8,%9}, {%0,%1,%2,%3};\n"
        : "+f"(c[0]), "+f"(c[1]), "+f"(c[2]), "+f"(c[3])
        : "r"(a[0]), "r"(a[1]), "r"(a[2]), "r"(a[3]), "r"(b[0]), "r"(b[1]));
}
__device__ __forceinline__ uint2 f4_to_h4(float4 v) {
    __half2 h01 = __floats2half2_rn(v.x, v.y);
    __half2 h23 = __floats2half2_rn(v.z, v.w);
    uint2 u;
    u.x = *reinterpret_cast<uint32_t*>(&h01);
    u.y = *reinterpret_cast<uint32_t*>(&h23);
    return u;
}

// ============================ pe =================================
__global__ void pe_kernel(float* __restrict__ pe) {
    int i = blockIdx.x;
    int j = threadIdx.x;
    double div = exp(-(double)j * 9.210340371976184 / 128.0);
    double a = (1023.0 - (double)i) * div;
    pe[i * KD + 2 * j]     = (float)sin(a);
    pe[i * KD + 2 * j + 1] = (float)cos(a);
}

// ============ proj via fp16 big/small split (3 x m16n8k16), 512 thr =========
#define PHSTR 40
#define PH_AB 0
#define PH_AS 5120
#define PH_WB 10240
#define PH_WS 15360
#define PJ_SMEM 40960

__global__ __launch_bounds__(512) void proj_mma(
    const float* __restrict__ A, const float* __restrict__ W,
    const float* __restrict__ bias, float* __restrict__ C,
    int M, int wStride, int cStride,
    const float* __restrict__ W2, const float* __restrict__ bias2,
    float* __restrict__ C2, int zSplit)
{
    extern __shared__ float sp[];
    __half* sph = (__half*)sp;
    int m0 = blockIdx.x * 128, n0 = blockIdx.y * 128;
    int z = blockIdx.z;
    if (z >= zSplit) { W = W2; bias = bias2; C = C2; z -= zSplit; }
    W += (long long)z * wStride;
    C += (long long)z * cStride;
    if (bias) bias += z * 256;
    int tid = threadIdx.x;
    int wid = tid >> 5, lane = tid & 31;
    int wy = wid >> 2, wx = wid & 3;
    int g = lane >> 2, t = lane & 3;
    float acc[2][4][4] = {};

    for (int k0 = 0; k0 < 256; k0 += 32) {
        #pragma unroll
        for (int it = 0; it < 2; it++) {
            int e = tid + 512 * it;
            int r = e >> 3, f = e & 7;
            int row = m0 + r;
            float4 a4 = (row < M) ? *(const float4*)&A[(long long)row * 256 + k0 + f * 4]
                                  : make_float4(0.f, 0.f, 0.f, 0.f);
            uint2 ah = f4_to_h4(a4);
            float2 af01 = __half22float2(*reinterpret_cast<__half2*>(&ah.x));
            float2 af23 = __half22float2(*reinterpret_cast<__half2*>(&ah.y));
            uint2 al = f4_to_h4(make_float4(a4.x - af01.x, a4.y - af01.y,
                                            a4.z - af23.x, a4.w - af23.y));
            *(uint2*)&sph[PH_AB + r * PHSTR + f * 4] = ah;
            *(uint2*)&sph[PH_AS + r * PHSTR + f * 4] = al;
            float4 w4 = *(const float4*)&W[(long long)(n0 + r) * 256 + k0 + f * 4];
            uint2 wh = f4_to_h4(w4);
            float2 wf01 = __half22float2(*reinterpret_cast<__half2*>(&wh.x));
            float2 wf23 = __half22float2(*reinterpret_cast<__half2*>(&wh.y));
            uint2 wl = f4_to_h4(make_float4(w4.x - wf01.x, w4.y - wf01.y,
                                            w4.z - wf23.x, w4.w - wf23.y));
            *(uint2*)&sph[PH_WB + r * PHSTR + f * 4] = wh;
            *(uint2*)&sph[PH_WS + r * PHSTR + f * 4] = wl;
        }
        __syncthreads();
        #pragma unroll
        for (int k0i = 0; k0i < 2; k0i++) {
            int kk = k0i * 16;
            uint32_t aB[2][4], aS[2][4], bB[4][2], bS[4][2];
            #pragma unroll
            for (int mi = 0; mi < 2; mi++) {
                int r0 = wy * 32 + mi * 16;
                aB[mi][0] = *(const uint32_t*)&sph[PH_AB + (r0 + g) * PHSTR + kk + 2 * t];
                aB[mi][1] = *(const uint32_t*)&sph[PH_AB + (r0 + g + 8) * PHSTR + kk + 2 * t];
                aB[mi][2] = *(const uint32_t*)&sph[PH_AB + (r0 + g) * PHSTR + kk + 2 * t + 8];
                aB[mi][3] = *(const uint32_t*)&sph[PH_AB + (r0 + g + 8) * PHSTR + kk + 2 * t + 8];
                aS[mi][0] = *(const uint32_t*)&sph[PH_AS + (r0 + g) * PHSTR + kk + 2 * t];
                aS[mi][1] = *(const uint32_t*)&sph[PH_AS + (r0 + g + 8) * PHSTR + kk + 2 * t];
                aS[mi][2] = *(const uint32_t*)&sph[PH_AS + (r0 + g) * PHSTR + kk + 2 * t + 8];
                aS[mi][3] = *(const uint32_t*)&sph[PH_AS + (r0 + g + 8) * PHSTR + kk + 2 * t + 8];
            }
            #pragma unroll
            for (int ni = 0; ni < 4; ni++) {
                int c0 = wx * 32 + ni * 8;
                bB[ni][0] = *(const uint32_t*)&sph[PH_WB + (c0 + g) * PHSTR + kk + 2 * t];
                bB[ni][1] = *(const uint32_t*)&sph[PH_WB + (c0 + g) * PHSTR + kk + 2 * t + 8];
                bS[ni][0] = *(const uint32_t*)&sph[PH_WS + (c0 + g) * PHSTR + kk + 2 * t];
                bS[ni][1] = *(const uint32_t*)&sph[PH_WS + (c0 + g) * PHSTR + kk + 2 * t + 8];
            }
            #pragma unroll
            for (int mi = 0; mi < 2; mi++)
                #pragma unroll
                for (int ni = 0; ni < 4; ni++) {
                    mma_f16(acc[mi][ni], aB[mi], bS[ni]);
                    mma_f16(acc[mi][ni], aS[mi], bB[ni]);
                    mma_f16(acc[mi][ni], aB[mi], bB[ni]);
                }
        }
        __syncthreads();
    }
    #pragma unroll
    for (int mi = 0; mi < 2; mi++) {
        int r1 = m0 + wy * 32 + mi * 16 + g;
        int r2 = r1 + 8;
        #pragma unroll
        for (int ni = 0; ni < 4; ni++) {
            int cx = wx * 32 + ni * 8 + 2 * t;
            float b0 = bias ? bias[n0 + cx] : 0.f;
            float b1 = bias ? bias[n0 + cx + 1] : 0.f;
            if (r1 < M)
                *(float2*)&C[(long long)r1 * 256 + n0 + cx] =
                    make_float2(acc[mi][ni][0] + b0, acc[mi][ni][1] + b1);
            if (r2 < M)
                *(float2*)&C[(long long)r2 * 256 + n0 + cx] =
                    make_float2(acc[mi][ni][2] + b0, acc[mi][ni][3] + b1);
        }
    }
}

// ============ scores: fp16 m16n8k16 MMA, banded G, fp16 ews out (R13) =======
#define HSTR 40
#define QUH_O 0
#define KTH_O 5120
#define QVH_O 10240
#define PDH_O 15400
#define G_O   12832
#define GSTR  260
#define SMAX_O (G_O + 128 * GSTR)
#define SSUM_O (SMAX_O + 512)
#define SC_FLOATS (SSUM_O + 512)
#define SC_SMEM (SC_FLOATS * 4)

__global__ __launch_bounds__(256, 1) void scores_mma_kernel(
    const float* __restrict__ q, const float* __restrict__ kmat,
    const float* __restrict__ p, const float* __restrict__ pbu,
    const float* __restrict__ pbv, __half* __restrict__ ews,
    float2* __restrict__ gstats)
{
    extern __shared__ float sm[];
    __half* smh = (__half*)sm;
    int q0 = blockIdx.x * 128, m0 = blockIdx.y * 128;
    int bh = blockIdx.z;
    int b = bh >> 3, h = bh & 7;
    int tid = threadIdx.x;
    int wid = tid >> 5, lane = tid & 31;
    int wy = wid >> 2, wx = wid & 3;
    int g = lane >> 2, t = lane & 3;

    int dlo = m0 - q0 + 3969;
    int da  = dlo >> 11;
    bool boundary = ((dlo >> 11) != ((dlo + 254) >> 11));

    const float* qb = q + (long long)b * KTQ * 256 + h * 32;
    #pragma unroll
    for (int it = 0; it < 4; it++) {
        int e = tid + 256 * it;
        int r = e >> 3, fj = e & 7;
        float4 bu4 = *(const float4*)&pbu[h * 32 + fj * 4];
        float4 a = *(const float4*)&qb[(long long)(q0 + r) * 256 + fj * 4];
        a.x += bu4.x; a.y += bu4.y; a.z += bu4.z; a.w += bu4.w;
        *(uint2*)&smh[QUH_O + r * HSTR + fj * 4] = f4_to_h4(a);
        float4 kk4 = *(const float4*)&kmat[(long long)(m0 + r) * 256 + h * 32 + fj * 4];
        *(uint2*)&smh[KTH_O + r * HSTR + fj * 4] = f4_to_h4(kk4);
    }
    #pragma unroll
    for (int it = 0; it < 5; it++) {
        int e = tid + 256 * it;
        if (e < 129 * 8) {
            int r = e >> 3, fj = e & 7;
            float4 bv4 = *(const float4*)&pbv[h * 32 + fj * 4];
            int rv = q0 + da + r; if (rv > KTQ - 1) rv = KTQ - 1;
            float4 v = *(const float4*)&qb[(long long)rv * 256 + fj * 4];
            v.x += bv4.x; v.y += bv4.y; v.z += bv4.z; v.w += bv4.w;
            *(uint2*)&smh[QVH_O + r * HSTR + fj * 4] = f4_to_h4(v);
        }
    }
    #pragma unroll
    for (int it = 0; it < 8; it++) {
        int e = tid + 256 * it;
        int r = e >> 3, fj = e & 7;
        int d = dlo + r;
        int cm = d & 2047;
        float4 v = make_float4(0.f, 0.f, 0.f, 0.f);
        if (cm > 0 && r < 255)
            v = *(const float4*)&p[(long long)(cm - 1) * 256 + h * 32 + fj * 4];
        *(uint2*)&smh[PDH_O + r * HSTR + fj * 4] = f4_to_h4(v);
    }
    __syncthreads();

    // ---- phase 1: banded G[r][ix] = Qv_sh[r] . Pd[ix], fp16 k16 ----
    if (!boundary) {
        int s0b = (wy == 0) ? 64 : 0;
        float accg[4][6][4] = {};
        #pragma unroll
        for (int k0 = 0; k0 < 2; k0++) {
            int kk = k0 * 16;
            uint32_t a[4][4], bb[6][2];
            #pragma unroll
            for (int mi = 0; mi < 4; mi++) {
                int r0 = wy * 64 + mi * 16;
                a[mi][0] = *(const uint32_t*)&smh[QVH_O + (r0 + g) * HSTR + kk + 2 * t];
                a[mi][1] = *(const uint32_t*)&smh[QVH_O + (r0 + g + 8) * HSTR + kk + 2 * t];
                a[mi][2] = *(const uint32_t*)&smh[QVH_O + (r0 + g) * HSTR + kk + 2 * t + 8];
                a[mi][3] = *(const uint32_t*)&smh[QVH_O + (r0 + g + 8) * HSTR + kk + 2 * t + 8];
            }
            #pragma unroll
            for (int ni = 0; ni < 6; ni++) {
                int c0 = s0b + (wx * 6 + ni) * 8;
                bb[ni][0] = *(const uint32_t*)&smh[PDH_O + (c0 + g) * HSTR + kk + 2 * t];
                bb[ni][1] = *(const uint32_t*)&smh[PDH_O + (c0 + g) * HSTR + kk + 2 * t + 8];
            }
            #pragma unroll
            for (int mi = 0; mi < 4; mi++)
                #pragma unroll
                for (int ni = 0; ni < 6; ni++)
                    mma_f16(accg[mi][ni], a[mi], bb[ni]);
        }
        #pragma unroll
        for (int mi = 0; mi < 4; mi++) {
            int r1 = wy * 64 + mi * 16 + g;
            #pragma unroll
            for (int ni = 0; ni < 6; ni++) {
                int cx = s0b + (wx * 6 + ni) * 8 + 2 * t;
                *(float2*)&sm[G_O + r1 * GSTR + cx] =
                    make_float2(accg[mi][ni][0], accg[mi][ni][1]);
                *(float2*)&sm[G_O + (r1 + 8) * GSTR + cx] =
                    make_float2(accg[mi][ni][2], accg[mi][ni][3]);
            }
        }
    } else {
        int trb = (tid >> 4) * 8, tcb = (tid & 15) * 8;
        #pragma unroll
        for (int i = 0; i < 8; i++) {
            int rr = trb + i;
            #pragma unroll
            for (int j = 0; j < 8; j++) {
                int c = tcb + j;
                int ix = c - rr + 127;
                int d = dlo + ix;
                int tt = rr + (d >> 11) - da;
                float s = 0.f;
                #pragma unroll
                for (int k = 0; k < 32; k++)
                    s += __half2float(smh[QVH_O + tt * HSTR + k])
                       * __half2float(smh[PDH_O + ix * HSTR + k]);
                sm[G_O + rr * GSTR + ix] = s;
            }
        }
    }
    __syncthreads();

    // ---- phase 2: ac = Qu . K^T, fp16 k16 ----
    float acc[4][4][4] = {};
    #pragma unroll
    for (int k0 = 0; k0 < 2; k0++) {
        int kk = k0 * 16;
        uint32_t a[4][4], bb[4][2];
        #pragma unroll
        for (int mi = 0; mi < 4; mi++) {
            int r0 = wy * 64 + mi * 16;
            a[mi][0] = *(const uint32_t*)&smh[QUH_O + (r0 + g) * HSTR + kk + 2 * t];
            a[mi][1] = *(const uint32_t*)&smh[QUH_O + (r0 + g + 8) * HSTR + kk + 2 * t];
            a[mi][2] = *(const uint32_t*)&smh[QUH_O + (r0 + g) * HSTR + kk + 2 * t + 8];
            a[mi][3] = *(const uint32_t*)&smh[QUH_O + (r0 + g + 8) * HSTR + kk + 2 * t + 8];
        }
        #pragma unroll
        for (int ni = 0; ni < 4; ni++) {
            int c0 = wx * 32 + ni * 8;
            bb[ni][0] = *(const uint32_t*)&smh[KTH_O + (c0 + g) * HSTR + kk + 2 * t];
            bb[ni][1] = *(const uint32_t*)&smh[KTH_O + (c0 + g) * HSTR + kk + 2 * t + 8];
        }
        #pragma unroll
        for (int mi = 0; mi < 4; mi++)
            #pragma unroll
            for (int ni = 0; ni < 4; ni++)
                mma_f16(acc[mi][ni], a[mi], bb[ni]);
    }

    // ---- combine with bd, scale ----
    const float sc = 0.17677669529663687f;
    #pragma unroll
    for (int mi = 0; mi < 4; mi++) {
        int r1 = wy * 64 + mi * 16 + g;
        int r2 = r1 + 8;
        #pragma unroll
        for (int ni = 0; ni < 4; ni++) {
            int cx = wx * 32 + ni * 8 + 2 * t;
            acc[mi][ni][0] = (acc[mi][ni][0] + sm[G_O + r1 * GSTR + cx     - r1 + 127]) * sc;
            acc[mi][ni][1] = (acc[mi][ni][1] + sm[G_O + r1 * GSTR + cx + 1 - r1 + 127]) * sc;
            acc[mi][ni][2] = (acc[mi][ni][2] + sm[G_O + r2 * GSTR + cx     - r2 + 127]) * sc;
            acc[mi][ni][3] = (acc[mi][ni][3] + sm[G_O + r2 * GSTR + cx + 1 - r2 + 127]) * sc;
        }
    }

    // ---- row-tile max reduce ----
    __syncthreads();
    float rm1[4], rm2[4];
    #pragma unroll
    for (int mi = 0; mi < 4; mi++) {
        int lr1 = wy * 64 + mi * 16 + g;
        int lr2 = lr1 + 8;
        float mx1 = -1e30f, mx2 = -1e30f;
        #pragma unroll
        for (int ni = 0; ni < 4; ni++) {
            mx1 = fmaxf(mx1, fmaxf(acc[mi][ni][0], acc[mi][ni][1]));
            mx2 = fmaxf(mx2, fmaxf(acc[mi][ni][2], acc[mi][ni][3]));
        }
        mx1 = fmaxf(mx1, __shfl_xor_sync(0xffffffffu, mx1, 1));
        mx1 = fmaxf(mx1, __shfl_xor_sync(0xffffffffu, mx1, 2));
        mx2 = fmaxf(mx2, __shfl_xor_sync(0xffffffffu, mx2, 1));
        mx2 = fmaxf(mx2, __shfl_xor_sync(0xffffffffu, mx2, 2));
        if (t == 0) {
            sm[SMAX_O + lr1 * 4 + wx] = mx1;
            sm[SMAX_O + lr2 * 4 + wx] = mx2;
        }
    }
    __syncthreads();

    // ---- exp + store fp16 + sum reduce ----
    #pragma unroll
    for (int mi = 0; mi < 4; mi++) {
        int lr1 = wy * 64 + mi * 16 + g;
        int lr2 = lr1 + 8;
        float a1 = fmaxf(fmaxf(sm[SMAX_O + lr1 * 4], sm[SMAX_O + lr1 * 4 + 1]),
                         fmaxf(sm[SMAX_O + lr1 * 4 + 2], sm[SMAX_O + lr1 * 4 + 3]));
        float a2 = fmaxf(fmaxf(sm[SMAX_O + lr2 * 4], sm[SMAX_O + lr2 * 4 + 1]),
                         fmaxf(sm[SMAX_O + lr2 * 4 + 2], sm[SMAX_O + lr2 * 4 + 3]));
        rm1[mi] = a1; rm2[mi] = a2;
        long long grow1 = ((long long)bh * KTQ + q0 + lr1) * KS + m0;
        long long grow2 = grow1 + 8 * KS;
        float s1 = 0.f, s2 = 0.f;
        #pragma unroll
        for (int ni = 0; ni < 4; ni++) {
            int cx = wx * 32 + ni * 8 + 2 * t;
            float e0 = __expf(acc[mi][ni][0] - a1);
            float e1 = __expf(acc[mi][ni][1] - a1);
            float e2 = __expf(acc[mi][ni][2] - a2);
            float e3 = __expf(acc[mi][ni][3] - a2);
            s1 += e0 + e1;
            s2 += e2 + e3;
            *(__half2*)&ews[grow1 + cx] = __floats2half2_rn(e0, e1);
            *(__half2*)&ews[grow2 + cx] = __floats2half2_rn(e2, e3);
        }
        s1 += __shfl_xor_sync(0xffffffffu, s1, 1);
        s1 += __shfl_xor_sync(0xffffffffu, s1, 2);
        s2 += __shfl_xor_sync(0xffffffffu, s2, 1);
        s2 += __shfl_xor_sync(0xffffffffu, s2, 2);
        if (t == 0) {
            sm[SSUM_O + lr1 * 4 + wx] = s1;
            sm[SSUM_O + lr2 * 4 + wx] = s2;
        }
    }
    __syncthreads();
    if (wx == 0 && t == 0) {
        int my = m0 >> 7;
        long long sb = ((long long)bh * 8 + my) * KTQ + q0;
        #pragma unroll
        for (int mi = 0; mi < 4; mi++) {
            int lr1 = wy * 64 + mi * 16 + g;
            int lr2 = lr1 + 8;
            float s1 = sm[SSUM_O + lr1 * 4] + sm[SSUM_O + lr1 * 4 + 1]
                     + sm[SSUM_O + lr1 * 4 + 2] + sm[SSUM_O + lr1 * 4 + 3];
            float s2 = sm[SSUM_O + lr2 * 4] + sm[SSUM_O + lr2 * 4 + 1]
                     + sm[SSUM_O + lr2 * 4 + 2] + sm[SSUM_O + lr2 * 4 + 3];
            gstats[sb + lr1] = make_float2(rm1[mi], s1);
            gstats[sb + lr2] = make_float2(rm2[mi], s2);
        }
    }
}

// ===== av: raw fp16 e as A operand, fp16 V as B, fac folded in epilogue =====
#define AHSTR 72
#define AVH_A 0
#define AVH_V (128 * AHSTR)
#define AV_M 5760
#define AV_I 5888
#define AV_S 6016
#define AV_F 8064
#define AV_SMEM ((8064 + 1024) * 4)

__global__ __launch_bounds__(256) void av_fused(
    const __half* __restrict__ ews, float* __restrict__ ws,
    const float* __restrict__ vmat,
    const float2* __restrict__ gstats, float* __restrict__ ao)
{
    extern __shared__ float sv[];
    __half* svh = (__half*)sv;
    float2* sSt = (float2*)(sv + AV_S);
    int q0 = blockIdx.x * 128;
    int bh = blockIdx.y;
    int b = bh >> 3, h = bh & 7;
    int tid = threadIdx.x;
    int wid = tid >> 5, lane = tid & 31;
    int g = lane >> 2, t = lane & 3;

    for (int idx = tid; idx < 1024; idx += 256)
        sSt[idx] = gstats[(((long long)bh * 8 + (idx >> 7)) << 12) + q0 + (idx & 127)];
    __syncthreads();
    if (tid < 128) {
        float M = -1e30f;
        #pragma unroll
        for (int mt = 0; mt < 8; mt++) M = fmaxf(M, sSt[mt * 128 + tid].x);
        float s = 0.f;
        #pragma unroll
        for (int mt = 0; mt < 8; mt++)
            s += sSt[mt * 128 + tid].y * __expf(sSt[mt * 128 + tid].x - M);
        sv[AV_M + tid] = M;
        sv[AV_I + tid] = 1.f / s;
    }
    __syncthreads();
    for (int idx = tid; idx < 1024; idx += 256) {
        int r = idx & 127;
        sv[AV_F + idx] = __expf(sSt[idx].x - sv[AV_M + r]) * sv[AV_I + r];
    }
    __syncthreads();

    const __half* ewsrow = ews + ((long long)bh * KTQ + q0) * KS;
    float* wsrow = ws + ((long long)bh * KTQ + q0) * KS;
    float acc[4][4] = {};

    for (int s0 = 0; s0 < KS; s0 += 64) {
        int mt = s0 >> 7;
        #pragma unroll
        for (int it = 0; it < 4; it++) {
            int e = tid + 256 * it;
            int r = e >> 3, f = e & 7;
            long long off = (long long)r * KS + s0 + f * 8;
            uint4 rh = *(const uint4*)&ewsrow[off];
            *(uint4*)&svh[AVH_A + r * AHSTR + f * 8] = rh;
            float fac = sv[AV_F + mt * 128 + r];
            float2 p0 = __half22float2(*reinterpret_cast<__half2*>(&rh.x));
            float2 p1 = __half22float2(*reinterpret_cast<__half2*>(&rh.y));
            float2 p2 = __half22float2(*reinterpret_cast<__half2*>(&rh.z));
            float2 p3 = __half22float2(*reinterpret_cast<__half2*>(&rh.w));
            float4 o0 = make_float4(p0.x * fac, p0.y * fac, p1.x * fac, p1.y * fac);
            float4 o1 = make_float4(p2.x * fac, p2.y * fac, p3.x * fac, p3.y * fac);
            *(float4*)&wsrow[off]     = o0;
            *(float4*)&wsrow[off + 4] = o1;
        }
        #pragma unroll
        for (int it = 0; it < 8; it++) {
            int e = tid + 256 * it;
            int k = e >> 5, n = e & 31;
            svh[AVH_V + n * AHSTR + k] =
                __float2half_rn(vmat[(long long)(s0 + k) * 256 + h * 32 + n]);
        }
        __syncthreads();

        int r0 = wid * 16;
        float accC[4][4] = {};
        #pragma unroll
        for (int k0 = 0; k0 < 4; k0++) {
            int kk = k0 * 16;
            uint32_t a[4];
            a[0] = *(const uint32_t*)&svh[AVH_A + (r0 + g) * AHSTR + kk + 2 * t];
            a[1] = *(const uint32_t*)&svh[AVH_A + (r0 + g + 8) * AHSTR + kk + 2 * t];
            a[2] = *(const uint32_t*)&svh[AVH_A + (r0 + g) * AHSTR + kk + 2 * t + 8];
            a[3] = *(const uint32_t*)&svh[AVH_A + (r0 + g + 8) * AHSTR + kk + 2 * t + 8];
            #pragma unroll
            for (int ni = 0; ni < 4; ni++) {
                uint32_t bb[2];
                bb[0] = *(const uint32_t*)&svh[AVH_V + (ni * 8 + g) * AHSTR + kk + 2 * t];
                bb[1] = *(const uint32_t*)&svh[AVH_V + (ni * 8 + g) * AHSTR + kk + 2 * t + 8];
                mma_f16(accC[ni], a, bb);
            }
        }
        float facA = sv[AV_F + mt * 128 + r0 + g];
        float facB = sv[AV_F + mt * 128 + r0 + g + 8];
        #pragma unroll
        for (int ni = 0; ni < 4; ni++) {
            acc[ni][0] += facA * accC[ni][0];
            acc[ni][1] += facA * accC[ni][1];
            acc[ni][2] += facB * accC[ni][2];
            acc[ni][3] += facB * accC[ni][3];
        }
        __syncthreads();
    }
    int r1 = q0 + wid * 16 + g;
    float* aob = ao + ((long long)b * KTQ + r1) * 256 + h * 32;
    #pragma unroll
    for (int ni = 0; ni < 4; ni++) {
        int cx = ni * 8 + 2 * t;
        *(float2*)&aob[cx]           = make_float2(acc[ni][0], acc[ni][1]);
        *(float2*)&aob[8 * 256 + cx] = make_float2(acc[ni][2], acc[ni][3]);
    }
}

// ---------------------------------------------------------------------------
extern "C" void kernel_launch(void* const* d_in, const int* in_sizes, int n_in,
                              void* d_out, int out_size)
{
    const float* vis  = (const float*)d_in[0];
    const float* mem  = (const float*)d_in[1];
    const float* Wq   = (const float*)d_in[3];
    const float* bq   = (const float*)d_in[4];
    const float* Wk   = (const float*)d_in[5];
    const float* bk   = (const float*)d_in[6];
    const float* Wv   = (const float*)d_in[7];
    const float* bv   = (const float*)d_in[8];
    const float* Wo   = (const float*)d_in[9];
    const float* bo   = (const float*)d_in[10];
    const float* Wpos = (const float*)d_in[11];
    const float* pbu  = (const float*)d_in[12];
    const float* pbv  = (const float*)d_in[13];

    float* out    = (float*)d_out;
    float* out_ws = out + XE;

    float* scratch = nullptr;
    cudaGetSymbolAddress((void**)&scratch, g_scratch);
    __half* ews = nullptr;
    cudaGetSymbolAddress((void**)&ews, g_ews);
    float* pe = scratch;
    float* pp = pe + 524032;
    float* kk = pp + 4 * 524032;
    float* vv = kk + 4 * 262144;
    float* qq = vv + 4 * 262144;
    float* xx = qq + XE;
    float* ao = xx + XE;
    float2* gstats = (float2*)(ao + XE);

    cudaFuncSetAttribute(scores_mma_kernel,
        cudaFuncAttributeMaxDynamicSharedMemorySize, SC_SMEM);
    cudaFuncSetAttribute(proj_mma,
        cudaFuncAttributeMaxDynamicSharedMemorySize, PJ_SMEM);
    cudaFuncSetAttribute(av_fused,
        cudaFuncAttributeMaxDynamicSharedMemorySize, AV_SMEM);

    pe_kernel<<<KP, 128>>>(pe);

    proj_mma<<<dim3(8, 2, 2 * KL), 512, PJ_SMEM>>>(mem, Wk, bk, kk, KS, 65536, 262144,
                                                   Wv, bv, vv, KL);
    proj_mma<<<dim3(16, 2, KL), 512, PJ_SMEM>>>(pe, Wpos, nullptr, pp, KP, 65536, 524032,
                                                nullptr, nullptr, nullptr, 1 << 30);

    const float* cur = vis;
    for (int l = 0; l < KL; l++) {
        proj_mma<<<dim3(64, 2, 1), 512, PJ_SMEM>>>(cur, Wq + l * 65536, bq + l * 256,
                                                   qq, KB * KTQ, 0, 0,
                                                   nullptr, nullptr, nullptr, 1 << 30);
        float* wsl = out_ws + (long long)l * KB * KH * KTQ * KS;
        scores_mma_kernel<<<dim3(32, 8, 16), 256, SC_SMEM>>>(
            qq, kk + l * 262144, pp + l * 524032,
            pbu + l * 256, pbv + l * 256, ews, gstats);
        av_fused<<<dim3(32, 16), 256, AV_SMEM>>>(ews, wsl, vv + l * 262144, gstats, ao);
        float* nxt = (l == KL - 1) ? out : xx;
        proj_mma<<<dim3(64, 2, 1), 512, PJ_SMEM>>>(ao, Wo + l * 65536, bo + l * 256,
                                                   nxt, KB * KTQ, 0, 0,
                                                   nullptr, nullptr, nullptr, 1 << 30);
        cur = nxt;
    }
}

// round 16
// speedup vs baseline: 1.2105x; 1.0590x over previous
#include <cuda_runtime.h>
#include <cuda_fp16.h>
#include <math.h>
#include <stdint.h>

#define KB   2
#define KTQ  4096
#define KS   1024
#define KD   256
#define KH   8
#define KL   4
#define KP   2047
#define XE   (KB*KTQ*KD)

__device__ float g_scratch[12057344];
__device__ __half g_ews[67108864];

// ===================== mma.sync fp16 m16n8k16 ========================
__device__ __forceinline__ void mma_f16(float* c, const uint32_t* a, const uint32_t* b) {
    asm volatile("mma.sync.aligned.m16n8k16.row.col.f32.f16.f16.f32 "
        "{%0,%1,%2,%3}, {%4,%5,%6,%7}, {%8,%9}, {%0,%1,%2,%3};\n"
        : "+f"(c[0]), "+f"(c[1]), "+f"(c[2]), "+f"(c[3])
        : "r"(a[0]), "r"(a[1]), "r"(a[2]), "r"(a[3]), "r"(b[0]), "r"(b[1]));
}
__device__ __forceinline__ uint2 f4_to_h4(float4 v) {
    __half2 h01 = __floats2half2_rn(v.x, v.y);
    __half2 h23 = __floats2half2_rn(v.z, v.w);
    uint2 u;
    u.x = *reinterpret_cast<uint32_t*>(&h01);
    u.y = *reinterpret_cast<uint32_t*>(&h23);
    return u;
}

// ============================ pe =================================
__global__ void pe_kernel(float* __restrict__ pe) {
    int i = blockIdx.x;
    int j = threadIdx.x;
    double div = exp(-(double)j * 9.210340371976184 / 128.0);
    double a = (1023.0 - (double)i) * div;
    pe[i * KD + 2 * j]     = (float)sin(a);
    pe[i * KD + 2 * j + 1] = (float)cos(a);
}

// ============ proj via fp16 big/small split (3 x m16n8k16), 512 thr =========
#define PHSTR 40
#define PH_AB 0
#define PH_AS 5120
#define PH_WB 10240
#define PH_WS 15360
#define PJ_SMEM 40960

__global__ __launch_bounds__(512) void proj_mma(
    const float* __restrict__ A, const float* __restrict__ W,
    const float* __restrict__ bias, float* __restrict__ C,
    int M, int wStride, int cStride,
    const float* __restrict__ W2, const float* __restrict__ bias2,
    float* __restrict__ C2, int zSplit)
{
    extern __shared__ float sp[];
    __half* sph = (__half*)sp;
    int m0 = blockIdx.x * 128, n0 = blockIdx.y * 128;
    int z = blockIdx.z;
    if (z >= zSplit) { W = W2; bias = bias2; C = C2; z -= zSplit; }
    W += (long long)z * wStride;
    C += (long long)z * cStride;
    if (bias) bias += z * 256;
    int tid = threadIdx.x;
    int wid = tid >> 5, lane = tid & 31;
    int wy = wid >> 2, wx = wid & 3;
    int g = lane >> 2, t = lane & 3;
    float acc[2][4][4] = {};

    for (int k0 = 0; k0 < 256; k0 += 32) {
        #pragma unroll
        for (int it = 0; it < 2; it++) {
            int e = tid + 512 * it;
            int r = e >> 3, f = e & 7;
            int row = m0 + r;
            float4 a4 = (row < M) ? *(const float4*)&A[(long long)row * 256 + k0 + f * 4]
                                  : make_float4(0.f, 0.f, 0.f, 0.f);
            uint2 ah = f4_to_h4(a4);
            float2 af01 = __half22float2(*reinterpret_cast<__half2*>(&ah.x));
            float2 af23 = __half22float2(*reinterpret_cast<__half2*>(&ah.y));
            uint2 al = f4_to_h4(make_float4(a4.x - af01.x, a4.y - af01.y,
                                            a4.z - af23.x, a4.w - af23.y));
            *(uint2*)&sph[PH_AB + r * PHSTR + f * 4] = ah;
            *(uint2*)&sph[PH_AS + r * PHSTR + f * 4] = al;
            float4 w4 = *(const float4*)&W[(long long)(n0 + r) * 256 + k0 + f * 4];
            uint2 wh = f4_to_h4(w4);
            float2 wf01 = __half22float2(*reinterpret_cast<__half2*>(&wh.x));
            float2 wf23 = __half22float2(*reinterpret_cast<__half2*>(&wh.y));
            uint2 wl = f4_to_h4(make_float4(w4.x - wf01.x, w4.y - wf01.y,
                                            w4.z - wf23.x, w4.w - wf23.y));
            *(uint2*)&sph[PH_WB + r * PHSTR + f * 4] = wh;
            *(uint2*)&sph[PH_WS + r * PHSTR + f * 4] = wl;
        }
        __syncthreads();
        #pragma unroll
        for (int k0i = 0; k0i < 2; k0i++) {
            int kk = k0i * 16;
            uint32_t aB[2][4], aS[2][4], bB[4][2], bS[4][2];
            #pragma unroll
            for (int mi = 0; mi < 2; mi++) {
                int r0 = wy * 32 + mi * 16;
                aB[mi][0] = *(const uint32_t*)&sph[PH_AB + (r0 + g) * PHSTR + kk + 2 * t];
                aB[mi][1] = *(const uint32_t*)&sph[PH_AB + (r0 + g + 8) * PHSTR + kk + 2 * t];
                aB[mi][2] = *(const uint32_t*)&sph[PH_AB + (r0 + g) * PHSTR + kk + 2 * t + 8];
                aB[mi][3] = *(const uint32_t*)&sph[PH_AB + (r0 + g + 8) * PHSTR + kk + 2 * t + 8];
                aS[mi][0] = *(const uint32_t*)&sph[PH_AS + (r0 + g) * PHSTR + kk + 2 * t];
                aS[mi][1] = *(const uint32_t*)&sph[PH_AS + (r0 + g + 8) * PHSTR + kk + 2 * t];
                aS[mi][2] = *(const uint32_t*)&sph[PH_AS + (r0 + g) * PHSTR + kk + 2 * t + 8];
                aS[mi][3] = *(const uint32_t*)&sph[PH_AS + (r0 + g + 8) * PHSTR + kk + 2 * t + 8];
            }
            #pragma unroll
            for (int ni = 0; ni < 4; ni++) {
                int c0 = wx * 32 + ni * 8;
                bB[ni][0] = *(const uint32_t*)&sph[PH_WB + (c0 + g) * PHSTR + kk + 2 * t];
                bB[ni][1] = *(const uint32_t*)&sph[PH_WB + (c0 + g) * PHSTR + kk + 2 * t + 8];
                bS[ni][0] = *(const uint32_t*)&sph[PH_WS + (c0 + g) * PHSTR + kk + 2 * t];
                bS[ni][1] = *(const uint32_t*)&sph[PH_WS + (c0 + g) * PHSTR + kk + 2 * t + 8];
            }
            #pragma unroll
            for (int mi = 0; mi < 2; mi++)
                #pragma unroll
                for (int ni = 0; ni < 4; ni++) {
                    mma_f16(acc[mi][ni], aB[mi], bS[ni]);
                    mma_f16(acc[mi][ni], aS[mi], bB[ni]);
                    mma_f16(acc[mi][ni], aB[mi], bB[ni]);
                }
        }
        __syncthreads();
    }
    #pragma unroll
    for (int mi = 0; mi < 2; mi++) {
        int r1 = m0 + wy * 32 + mi * 16 + g;
        int r2 = r1 + 8;
        #pragma unroll
        for (int ni = 0; ni < 4; ni++) {
            int cx = wx * 32 + ni * 8 + 2 * t;
            float b0 = bias ? bias[n0 + cx] : 0.f;
            float b1 = bias ? bias[n0 + cx + 1] : 0.f;
            if (r1 < M)
                *(float2*)&C[(long long)r1 * 256 + n0 + cx] =
                    make_float2(acc[mi][ni][0] + b0, acc[mi][ni][1] + b1);
            if (r2 < M)
                *(float2*)&C[(long long)r2 * 256 + n0 + cx] =
                    make_float2(acc[mi][ni][2] + b0, acc[mi][ni][3] + b1);
        }
    }
}

// ============ scores: fp16 MMA, banded G, coalesced fp16 ews out ============
#define HSTR 40
#define QUH_O 0
#define KTH_O 5120
#define QVH_O 10240
#define PDH_O 15400
#define G_O   12832
#define GSTR  260
#define EH_O  (G_O * 2)          // half-index alias of the dead G buffer
#define ESTR  136
#define SMAX_O (G_O + 128 * GSTR)
#define SSUM_O (SMAX_O + 512)
#define SC_FLOATS (SSUM_O + 512)
#define SC_SMEM (SC_FLOATS * 4)

__global__ __launch_bounds__(256, 1) void scores_mma_kernel(
    const float* __restrict__ q, const float* __restrict__ kmat,
    const float* __restrict__ p, const float* __restrict__ pbu,
    const float* __restrict__ pbv, __half* __restrict__ ews,
    float2* __restrict__ gstats)
{
    extern __shared__ float sm[];
    __half* smh = (__half*)sm;
    int q0 = blockIdx.x * 128, m0 = blockIdx.y * 128;
    int bh = blockIdx.z;
    int b = bh >> 3, h = bh & 7;
    int tid = threadIdx.x;
    int wid = tid >> 5, lane = tid & 31;
    int wy = wid >> 2, wx = wid & 3;
    int g = lane >> 2, t = lane & 3;

    int dlo = m0 - q0 + 3969;
    int da  = dlo >> 11;
    bool boundary = ((dlo >> 11) != ((dlo + 254) >> 11));

    const float* qb = q + (long long)b * KTQ * 256 + h * 32;
    #pragma unroll
    for (int it = 0; it < 4; it++) {
        int e = tid + 256 * it;
        int r = e >> 3, fj = e & 7;
        float4 bu4 = *(const float4*)&pbu[h * 32 + fj * 4];
        float4 a = *(const float4*)&qb[(long long)(q0 + r) * 256 + fj * 4];
        a.x += bu4.x; a.y += bu4.y; a.z += bu4.z; a.w += bu4.w;
        *(uint2*)&smh[QUH_O + r * HSTR + fj * 4] = f4_to_h4(a);
        float4 kk4 = *(const float4*)&kmat[(long long)(m0 + r) * 256 + h * 32 + fj * 4];
        *(uint2*)&smh[KTH_O + r * HSTR + fj * 4] = f4_to_h4(kk4);
    }
    #pragma unroll
    for (int it = 0; it < 5; it++) {
        int e = tid + 256 * it;
        if (e < 129 * 8) {
            int r = e >> 3, fj = e & 7;
            float4 bv4 = *(const float4*)&pbv[h * 32 + fj * 4];
            int rv = q0 + da + r; if (rv > KTQ - 1) rv = KTQ - 1;
            float4 v = *(const float4*)&qb[(long long)rv * 256 + fj * 4];
            v.x += bv4.x; v.y += bv4.y; v.z += bv4.z; v.w += bv4.w;
            *(uint2*)&smh[QVH_O + r * HSTR + fj * 4] = f4_to_h4(v);
        }
    }
    #pragma unroll
    for (int it = 0; it < 8; it++) {
        int e = tid + 256 * it;
        int r = e >> 3, fj = e & 7;
        int d = dlo + r;
        int cm = d & 2047;
        float4 v = make_float4(0.f, 0.f, 0.f, 0.f);
        if (cm > 0 && r < 255)
            v = *(const float4*)&p[(long long)(cm - 1) * 256 + h * 32 + fj * 4];
        *(uint2*)&smh[PDH_O + r * HSTR + fj * 4] = f4_to_h4(v);
    }
    __syncthreads();

    // ---- phase 1: banded G[r][ix] = Qv_sh[r] . Pd[ix], fp16 k16 ----
    if (!boundary) {
        int s0b = (wy == 0) ? 64 : 0;
        float accg[4][6][4] = {};
        #pragma unroll
        for (int k0 = 0; k0 < 2; k0++) {
            int kk = k0 * 16;
            uint32_t a[4][4], bb[6][2];
            #pragma unroll
            for (int mi = 0; mi < 4; mi++) {
                int r0 = wy * 64 + mi * 16;
                a[mi][0] = *(const uint32_t*)&smh[QVH_O + (r0 + g) * HSTR + kk + 2 * t];
                a[mi][1] = *(const uint32_t*)&smh[QVH_O + (r0 + g + 8) * HSTR + kk + 2 * t];
                a[mi][2] = *(const uint32_t*)&smh[QVH_O + (r0 + g) * HSTR + kk + 2 * t + 8];
                a[mi][3] = *(const uint32_t*)&smh[QVH_O + (r0 + g + 8) * HSTR + kk + 2 * t + 8];
            }
            #pragma unroll
            for (int ni = 0; ni < 6; ni++) {
                int c0 = s0b + (wx * 6 + ni) * 8;
                bb[ni][0] = *(const uint32_t*)&smh[PDH_O + (c0 + g) * HSTR + kk + 2 * t];
                bb[ni][1] = *(const uint32_t*)&smh[PDH_O + (c0 + g) * HSTR + kk + 2 * t + 8];
            }
            #pragma unroll
            for (int mi = 0; mi < 4; mi++)
                #pragma unroll
                for (int ni = 0; ni < 6; ni++)
                    mma_f16(accg[mi][ni], a[mi], bb[ni]);
        }
        #pragma unroll
        for (int mi = 0; mi < 4; mi++) {
            int r1 = wy * 64 + mi * 16 + g;
            #pragma unroll
            for (int ni = 0; ni < 6; ni++) {
                int cx = s0b + (wx * 6 + ni) * 8 + 2 * t;
                *(float2*)&sm[G_O + r1 * GSTR + cx] =
                    make_float2(accg[mi][ni][0], accg[mi][ni][1]);
                *(float2*)&sm[G_O + (r1 + 8) * GSTR + cx] =
                    make_float2(accg[mi][ni][2], accg[mi][ni][3]);
            }
        }
    } else {
        int trb = (tid >> 4) * 8, tcb = (tid & 15) * 8;
        #pragma unroll
        for (int i = 0; i < 8; i++) {
            int rr = trb + i;
            #pragma unroll
            for (int j = 0; j < 8; j++) {
                int c = tcb + j;
                int ix = c - rr + 127;
                int d = dlo + ix;
                int tt = rr + (d >> 11) - da;
                float s = 0.f;
                #pragma unroll
                for (int k = 0; k < 32; k++)
                    s += __half2float(smh[QVH_O + tt * HSTR + k])
                       * __half2float(smh[PDH_O + ix * HSTR + k]);
                sm[G_O + rr * GSTR + ix] = s;
            }
        }
    }
    __syncthreads();

    // ---- phase 2: ac = Qu . K^T, fp16 k16 ----
    float acc[4][4][4] = {};
    #pragma unroll
    for (int k0 = 0; k0 < 2; k0++) {
        int kk = k0 * 16;
        uint32_t a[4][4], bb[4][2];
        #pragma unroll
        for (int mi = 0; mi < 4; mi++) {
            int r0 = wy * 64 + mi * 16;
            a[mi][0] = *(const uint32_t*)&smh[QUH_O + (r0 + g) * HSTR + kk + 2 * t];
            a[mi][1] = *(const uint32_t*)&smh[QUH_O + (r0 + g + 8) * HSTR + kk + 2 * t];
            a[mi][2] = *(const uint32_t*)&smh[QUH_O + (r0 + g) * HSTR + kk + 2 * t + 8];
            a[mi][3] = *(const uint32_t*)&smh[QUH_O + (r0 + g + 8) * HSTR + kk + 2 * t + 8];
        }
        #pragma unroll
        for (int ni = 0; ni < 4; ni++) {
            int c0 = wx * 32 + ni * 8;
            bb[ni][0] = *(const uint32_t*)&smh[KTH_O + (c0 + g) * HSTR + kk + 2 * t];
            bb[ni][1] = *(const uint32_t*)&smh[KTH_O + (c0 + g) * HSTR + kk + 2 * t + 8];
        }
        #pragma unroll
        for (int mi = 0; mi < 4; mi++)
            #pragma unroll
            for (int ni = 0; ni < 4; ni++)
                mma_f16(acc[mi][ni], a[mi], bb[ni]);
    }

    // ---- combine with bd, scale ----
    const float sc = 0.17677669529663687f;
    #pragma unroll
    for (int mi = 0; mi < 4; mi++) {
        int r1 = wy * 64 + mi * 16 + g;
        int r2 = r1 + 8;
        #pragma unroll
        for (int ni = 0; ni < 4; ni++) {
            int cx = wx * 32 + ni * 8 + 2 * t;
            acc[mi][ni][0] = (acc[mi][ni][0] + sm[G_O + r1 * GSTR + cx     - r1 + 127]) * sc;
            acc[mi][ni][1] = (acc[mi][ni][1] + sm[G_O + r1 * GSTR + cx + 1 - r1 + 127]) * sc;
            acc[mi][ni][2] = (acc[mi][ni][2] + sm[G_O + r2 * GSTR + cx     - r2 + 127]) * sc;
            acc[mi][ni][3] = (acc[mi][ni][3] + sm[G_O + r2 * GSTR + cx + 1 - r2 + 127]) * sc;
        }
    }

    // ---- row-tile max reduce (G dead after this barrier -> reuse as E) ----
    __syncthreads();
    float rm1[4], rm2[4];
    #pragma unroll
    for (int mi = 0; mi < 4; mi++) {
        int lr1 = wy * 64 + mi * 16 + g;
        int lr2 = lr1 + 8;
        float mx1 = -1e30f, mx2 = -1e30f;
        #pragma unroll
        for (int ni = 0; ni < 4; ni++) {
            mx1 = fmaxf(mx1, fmaxf(acc[mi][ni][0], acc[mi][ni][1]));
            mx2 = fmaxf(mx2, fmaxf(acc[mi][ni][2], acc[mi][ni][3]));
        }
        mx1 = fmaxf(mx1, __shfl_xor_sync(0xffffffffu, mx1, 1));
        mx1 = fmaxf(mx1, __shfl_xor_sync(0xffffffffu, mx1, 2));
        mx2 = fmaxf(mx2, __shfl_xor_sync(0xffffffffu, mx2, 1));
        mx2 = fmaxf(mx2, __shfl_xor_sync(0xffffffffu, mx2, 2));
        if (t == 0) {
            sm[SMAX_O + lr1 * 4 + wx] = mx1;
            sm[SMAX_O + lr2 * 4 + wx] = mx2;
        }
    }
    __syncthreads();

    // ---- exp + stage E in smem + sum reduce ----
    #pragma unroll
    for (int mi = 0; mi < 4; mi++) {
        int lr1 = wy * 64 + mi * 16 + g;
        int lr2 = lr1 + 8;
        float a1 = fmaxf(fmaxf(sm[SMAX_O + lr1 * 4], sm[SMAX_O + lr1 * 4 + 1]),
                         fmaxf(sm[SMAX_O + lr1 * 4 + 2], sm[SMAX_O + lr1 * 4 + 3]));
        float a2 = fmaxf(fmaxf(sm[SMAX_O + lr2 * 4], sm[SMAX_O + lr2 * 4 + 1]),
                         fmaxf(sm[SMAX_O + lr2 * 4 + 2], sm[SMAX_O + lr2 * 4 + 3]));
        rm1[mi] = a1; rm2[mi] = a2;
        float s1 = 0.f, s2 = 0.f;
        #pragma unroll
        for (int ni = 0; ni < 4; ni++) {
            int cx = wx * 32 + ni * 8 + 2 * t;
            float e0 = __expf(acc[mi][ni][0] - a1);
            float e1 = __expf(acc[mi][ni][1] - a1);
            float e2 = __expf(acc[mi][ni][2] - a2);
            float e3 = __expf(acc[mi][ni][3] - a2);
            s1 += e0 + e1;
            s2 += e2 + e3;
            __half2 h0 = __floats2half2_rn(e0, e1);
            __half2 h1 = __floats2half2_rn(e2, e3);
            *(uint32_t*)&smh[EH_O + lr1 * ESTR + cx] = *reinterpret_cast<uint32_t*>(&h0);
            *(uint32_t*)&smh[EH_O + lr2 * ESTR + cx] = *reinterpret_cast<uint32_t*>(&h1);
        }
        s1 += __shfl_xor_sync(0xffffffffu, s1, 1);
        s1 += __shfl_xor_sync(0xffffffffu, s1, 2);
        s2 += __shfl_xor_sync(0xffffffffu, s2, 1);
        s2 += __shfl_xor_sync(0xffffffffu, s2, 2);
        if (t == 0) {
            sm[SSUM_O + lr1 * 4 + wx] = s1;
            sm[SSUM_O + lr2 * 4 + wx] = s2;
        }
    }
    __syncthreads();

    // ---- coalesced ews store: 16 lanes x 16B = full rows ----
    {
        long long gbase = ((long long)bh * KTQ + q0) * KS + m0;
        #pragma unroll
        for (int it = 0; it < 8; it++) {
            int e = tid + 256 * it;
            int r = e >> 4, f = e & 15;
            uint4 v = *(const uint4*)&smh[EH_O + r * ESTR + f * 8];
            *(uint4*)&ews[gbase + (long long)r * KS + f * 8] = v;
        }
    }
    if (wx == 0 && t == 0) {
        int my = m0 >> 7;
        long long sb = ((long long)bh * 8 + my) * KTQ + q0;
        #pragma unroll
        for (int mi = 0; mi < 4; mi++) {
            int lr1 = wy * 64 + mi * 16 + g;
            int lr2 = lr1 + 8;
            float s1 = sm[SSUM_O + lr1 * 4] + sm[SSUM_O + lr1 * 4 + 1]
                     + sm[SSUM_O + lr1 * 4 + 2] + sm[SSUM_O + lr1 * 4 + 3];
            float s2 = sm[SSUM_O + lr2 * 4] + sm[SSUM_O + lr2 * 4 + 1]
                     + sm[SSUM_O + lr2 * 4 + 2] + sm[SSUM_O + lr2 * 4 + 3];
            gstats[sb + lr1] = make_float2(rm1[mi], s1);
            gstats[sb + lr2] = make_float2(rm2[mi], s2);
        }
    }
}

// ===== av: raw fp16 e as A operand, fp16 V as B, fac folded in epilogue =====
#define AHSTR 72
#define AVH_A 0
#define AVH_V (128 * AHSTR)
#define AV_M 5760
#define AV_I 5888
#define AV_S 6016
#define AV_F 8064
#define AV_SMEM ((8064 + 1024) * 4)

__global__ __launch_bounds__(256) void av_fused(
    const __half* __restrict__ ews, float* __restrict__ ws,
    const float* __restrict__ vmat,
    const float2* __restrict__ gstats, float* __restrict__ ao)
{
    extern __shared__ float sv[];
    __half* svh = (__half*)sv;
    float2* sSt = (float2*)(sv + AV_S);
    int q0 = blockIdx.x * 128;
    int bh = blockIdx.y;
    int b = bh >> 3, h = bh & 7;
    int tid = threadIdx.x;
    int wid = tid >> 5, lane = tid & 31;
    int g = lane >> 2, t = lane & 3;

    for (int idx = tid; idx < 1024; idx += 256)
        sSt[idx] = gstats[(((long long)bh * 8 + (idx >> 7)) << 12) + q0 + (idx & 127)];
    __syncthreads();
    if (tid < 128) {
        float M = -1e30f;
        #pragma unroll
        for (int mt = 0; mt < 8; mt++) M = fmaxf(M, sSt[mt * 128 + tid].x);
        float s = 0.f;
        #pragma unroll
        for (int mt = 0; mt < 8; mt++)
            s += sSt[mt * 128 + tid].y * __expf(sSt[mt * 128 + tid].x - M);
        sv[AV_M + tid] = M;
        sv[AV_I + tid] = 1.f / s;
    }
    __syncthreads();
    for (int idx = tid; idx < 1024; idx += 256) {
        int r = idx & 127;
        sv[AV_F + idx] = __expf(sSt[idx].x - sv[AV_M + r]) * sv[AV_I + r];
    }
    __syncthreads();

    const __half* ewsrow = ews + ((long long)bh * KTQ + q0) * KS;
    float* wsrow = ws + ((long long)bh * KTQ + q0) * KS;
    float acc[4][4] = {};

    for (int s0 = 0; s0 < KS; s0 += 64) {
        int mt = s0 >> 7;
        #pragma unroll
        for (int it = 0; it < 4; it++) {
            int e = tid + 256 * it;
            int r = e >> 3, f = e & 7;
            long long off = (long long)r * KS + s0 + f * 8;
            uint4 rh = *(const uint4*)&ewsrow[off];
            *(uint4*)&svh[AVH_A + r * AHSTR + f * 8] = rh;
            float fac = sv[AV_F + mt * 128 + r];
            float2 p0 = __half22float2(*reinterpret_cast<__half2*>(&rh.x));
            float2 p1 = __half22float2(*reinterpret_cast<__half2*>(&rh.y));
            float2 p2 = __half22float2(*reinterpret_cast<__half2*>(&rh.z));
            float2 p3 = __half22float2(*reinterpret_cast<__half2*>(&rh.w));
            float4 o0 = make_float4(p0.x * fac, p0.y * fac, p1.x * fac, p1.y * fac);
            float4 o1 = make_float4(p2.x * fac, p2.y * fac, p3.x * fac, p3.y * fac);
            *(float4*)&wsrow[off]     = o0;
            *(float4*)&wsrow[off + 4] = o1;
        }
        #pragma unroll
        for (int it = 0; it < 8; it++) {
            int e = tid + 256 * it;
            int k = e >> 5, n = e & 31;
            svh[AVH_V + n * AHSTR + k] =
                __float2half_rn(vmat[(long long)(s0 + k) * 256 + h * 32 + n]);
        }
        __syncthreads();

        int r0 = wid * 16;
        float accC[4][4] = {};
        #pragma unroll
        for (int k0 = 0; k0 < 4; k0++) {
            int kk = k0 * 16;
            uint32_t a[4];
            a[0] = *(const uint32_t*)&svh[AVH_A + (r0 + g) * AHSTR + kk + 2 * t];
            a[1] = *(const uint32_t*)&svh[AVH_A + (r0 + g + 8) * AHSTR + kk + 2 * t];
            a[2] = *(const uint32_t*)&svh[AVH_A + (r0 + g) * AHSTR + kk + 2 * t + 8];
            a[3] = *(const uint32_t*)&svh[AVH_A + (r0 + g + 8) * AHSTR + kk + 2 * t + 8];
            #pragma unroll
            for (int ni = 0; ni < 4; ni++) {
                uint32_t bb[2];
                bb[0] = *(const uint32_t*)&svh[AVH_V + (ni * 8 + g) * AHSTR + kk + 2 * t];
                bb[1] = *(const uint32_t*)&svh[AVH_V + (ni * 8 + g) * AHSTR + kk + 2 * t + 8];
                mma_f16(accC[ni], a, bb);
            }
        }
        float facA = sv[AV_F + mt * 128 + r0 + g];
        float facB = sv[AV_F + mt * 128 + r0 + g + 8];
        #pragma unroll
        for (int ni = 0; ni < 4; ni++) {
            acc[ni][0] += facA * accC[ni][0];
            acc[ni][1] += facA * accC[ni][1];
            acc[ni][2] += facB * accC[ni][2];
            acc[ni][3] += facB * accC[ni][3];
        }
        __syncthreads();
    }
    int r1 = q0 + wid * 16 + g;
    float* aob = ao + ((long long)b * KTQ + r1) * 256 + h * 32;
    #pragma unroll
    for (int ni = 0; ni < 4; ni++) {
        int cx = ni * 8 + 2 * t;
        *(float2*)&aob[cx]           = make_float2(acc[ni][0], acc[ni][1]);
        *(float2*)&aob[8 * 256 + cx] = make_float2(acc[ni][2], acc[ni][3]);
    }
}

// ---------------------------------------------------------------------------
extern "C" void kernel_launch(void* const* d_in, const int* in_sizes, int n_in,
                              void* d_out, int out_size)
{
    const float* vis  = (const float*)d_in[0];
    const float* mem  = (const float*)d_in[1];
    const float* Wq   = (const float*)d_in[3];
    const float* bq   = (const float*)d_in[4];
    const float* Wk   = (const float*)d_in[5];
    const float* bk   = (const float*)d_in[6];
    const float* Wv   = (const float*)d_in[7];
    const float* bv   = (const float*)d_in[8];
    const float* Wo   = (const float*)d_in[9];
    const float* bo   = (const float*)d_in[10];
    const float* Wpos = (const float*)d_in[11];
    const float* pbu  = (const float*)d_in[12];
    const float* pbv  = (const float*)d_in[13];

    float* out    = (float*)d_out;
    float* out_ws = out + XE;

    float* scratch = nullptr;
    cudaGetSymbolAddress((void**)&scratch, g_scratch);
    __half* ews = nullptr;
    cudaGetSymbolAddress((void**)&ews, g_ews);
    float* pe = scratch;
    float* pp = pe + 524032;
    float* kk = pp + 4 * 524032;
    float* vv = kk + 4 * 262144;
    float* qq = vv + 4 * 262144;
    float* xx = qq + XE;
    float* ao = xx + XE;
    float2* gstats = (float2*)(ao + XE);

    cudaFuncSetAttribute(scores_mma_kernel,
        cudaFuncAttributeMaxDynamicSharedMemorySize, SC_SMEM);
    cudaFuncSetAttribute(proj_mma,
        cudaFuncAttributeMaxDynamicSharedMemorySize, PJ_SMEM);
    cudaFuncSetAttribute(av_fused,
        cudaFuncAttributeMaxDynamicSharedMemorySize, AV_SMEM);

    pe_kernel<<<KP, 128>>>(pe);

    proj_mma<<<dim3(8, 2, 2 * KL), 512, PJ_SMEM>>>(mem, Wk, bk, kk, KS, 65536, 262144,
                                                   Wv, bv, vv, KL);
    proj_mma<<<dim3(16, 2, KL), 512, PJ_SMEM>>>(pe, Wpos, nullptr, pp, KP, 65536, 524032,
                                                nullptr, nullptr, nullptr, 1 << 30);

    const float* cur = vis;
    for (int l = 0; l < KL; l++) {
        proj_mma<<<dim3(64, 2, 1), 512, PJ_SMEM>>>(cur, Wq + l * 65536, bq + l * 256,
                                                   qq, KB * KTQ, 0, 0,
                                                   nullptr, nullptr, nullptr, 1 << 30);
        float* wsl = out_ws + (long long)l * KB * KH * KTQ * KS;
        scores_mma_kernel<<<dim3(32, 8, 16), 256, SC_SMEM>>>(
            qq, kk + l * 262144, pp + l * 524032,
            pbu + l * 256, pbv + l * 256, ews, gstats);
        av_fused<<<dim3(32, 16), 256, AV_SMEM>>>(ews, wsl, vv + l * 262144, gstats, ao);
        float* nxt = (l == KL - 1) ? out : xx;
        proj_mma<<<dim3(64, 2, 1), 512, PJ_SMEM>>>(ao, Wo + l * 65536, bo + l * 256,
                                                   nxt, KB * KTQ, 0, 0,
                                                   nullptr, nullptr, nullptr, 1 << 30);
        cur = nxt;
    }
}

// round 17
// speedup vs baseline: 1.2461x; 1.0293x over previous
#include <cuda_runtime.h>
#include <cuda_fp16.h>
#include <math.h>
#include <stdint.h>

#define KB   2
#define KTQ  4096
#define KS   1024
#define KD   256
#define KH   8
#define KL   4
#define KP   2047
#define XE   (KB*KTQ*KD)

__device__ float g_scratch[12057344];
__device__ __half g_ews[67108864];

// ===================== mma.sync fp16 m16n8k16 ========================
__device__ __forceinline__ void mma_f16(float* c, const uint32_t* a, const uint32_t* b) {
    asm volatile("mma.sync.aligned.m16n8k16.row.col.f32.f16.f16.f32 "
        "{%0,%1,%2,%3}, {%4,%5,%6,%7}, {%8,%9}, {%0,%1,%2,%3};\n"
        : "+f"(c[0]), "+f"(c[1]), "+f"(c[2]), "+f"(c[3])
        : "r"(a[0]), "r"(a[1]), "r"(a[2]), "r"(a[3]), "r"(b[0]), "r"(b[1]));
}
__device__ __forceinline__ uint2 f4_to_h4(float4 v) {
    __half2 h01 = __floats2half2_rn(v.x, v.y);
    __half2 h23 = __floats2half2_rn(v.z, v.w);
    uint2 u;
    u.x = *reinterpret_cast<uint32_t*>(&h01);
    u.y = *reinterpret_cast<uint32_t*>(&h23);
    return u;
}

// ============================ pe =================================
__global__ void pe_kernel(float* __restrict__ pe) {
    int i = blockIdx.x;
    int j = threadIdx.x;
    double div = exp(-(double)j * 9.210340371976184 / 128.0);
    double a = (1023.0 - (double)i) * div;
    pe[i * KD + 2 * j]     = (float)sin(a);
    pe[i * KD + 2 * j + 1] = (float)cos(a);
}

// ====== proj: fp16 big/small split, double-buffered k pipeline, 512 thr =====
#define PHSTR 40
#define PH_AB 0
#define PH_AS 5120
#define PH_WB 10240
#define PH_WS 15360
#define PH_BUF 20480
#define PJ_SMEM 81920

__global__ __launch_bounds__(512) void proj_mma(
    const float* __restrict__ A, const float* __restrict__ W,
    const float* __restrict__ bias, float* __restrict__ C,
    int M, int wStride, int cStride,
    const float* __restrict__ W2, const float* __restrict__ bias2,
    float* __restrict__ C2, int zSplit)
{
    extern __shared__ float sp[];
    __half* sph = (__half*)sp;
    int m0 = blockIdx.x * 128, n0 = blockIdx.y * 128;
    int z = blockIdx.z;
    if (z >= zSplit) { W = W2; bias = bias2; C = C2; z -= zSplit; }
    W += (long long)z * wStride;
    C += (long long)z * cStride;
    if (bias) bias += z * 256;
    int tid = threadIdx.x;
    int wid = tid >> 5, lane = tid & 31;
    int wy = wid >> 2, wx = wid & 3;
    int g = lane >> 2, t = lane & 3;
    int lr = tid >> 3, lf = tid & 7;      // thread's staging row/col (+64 for it=1)
    int row0 = m0 + lr, row1 = m0 + lr + 64;
    float acc[2][4][4] = {};
    float4 aReg[2], wReg[2];

    // prologue: load k0 = 0
    aReg[0] = (row0 < M) ? *(const float4*)&A[(long long)row0 * 256 + lf * 4]
                         : make_float4(0.f, 0.f, 0.f, 0.f);
    aReg[1] = (row1 < M) ? *(const float4*)&A[(long long)row1 * 256 + lf * 4]
                         : make_float4(0.f, 0.f, 0.f, 0.f);
    wReg[0] = *(const float4*)&W[(long long)(n0 + lr) * 256 + lf * 4];
    wReg[1] = *(const float4*)&W[(long long)(n0 + lr + 64) * 256 + lf * 4];

    #pragma unroll 1
    for (int ki = 0; ki < 8; ki++) {
        int cb = (ki & 1) * PH_BUF;
        // convert + store current regs into buffer cb
        #pragma unroll
        for (int it = 0; it < 2; it++) {
            int r = lr + it * 64;
            float4 a4 = aReg[it];
            uint2 ah = f4_to_h4(a4);
            float2 af01 = __half22float2(*reinterpret_cast<__half2*>(&ah.x));
            float2 af23 = __half22float2(*reinterpret_cast<__half2*>(&ah.y));
            uint2 al = f4_to_h4(make_float4(a4.x - af01.x, a4.y - af01.y,
                                            a4.z - af23.x, a4.w - af23.y));
            *(uint2*)&sph[cb + PH_AB + r * PHSTR + lf * 4] = ah;
            *(uint2*)&sph[cb + PH_AS + r * PHSTR + lf * 4] = al;
            float4 w4 = wReg[it];
            uint2 wh = f4_to_h4(w4);
            float2 wf01 = __half22float2(*reinterpret_cast<__half2*>(&wh.x));
            float2 wf23 = __half22float2(*reinterpret_cast<__half2*>(&wh.y));
            uint2 wl = f4_to_h4(make_float4(w4.x - wf01.x, w4.y - wf01.y,
                                            w4.z - wf23.x, w4.w - wf23.y));
            *(uint2*)&sph[cb + PH_WB + r * PHSTR + lf * 4] = wh;
            *(uint2*)&sph[cb + PH_WS + r * PHSTR + lf * 4] = wl;
        }
        __syncthreads();
        // prefetch next chunk while doing mma on cb
        if (ki < 7) {
            int k0 = (ki + 1) * 32;
            aReg[0] = (row0 < M) ? *(const float4*)&A[(long long)row0 * 256 + k0 + lf * 4]
                                 : make_float4(0.f, 0.f, 0.f, 0.f);
            aReg[1] = (row1 < M) ? *(const float4*)&A[(long long)row1 * 256 + k0 + lf * 4]
                                 : make_float4(0.f, 0.f, 0.f, 0.f);
            wReg[0] = *(const float4*)&W[(long long)(n0 + lr) * 256 + k0 + lf * 4];
            wReg[1] = *(const float4*)&W[(long long)(n0 + lr + 64) * 256 + k0 + lf * 4];
        }
        #pragma unroll
        for (int k0i = 0; k0i < 2; k0i++) {
            int kk = k0i * 16;
            uint32_t aB[2][4], aS[2][4], bB[4][2], bS[4][2];
            #pragma unroll
            for (int mi = 0; mi < 2; mi++) {
                int r0 = wy * 32 + mi * 16;
                aB[mi][0] = *(const uint32_t*)&sph[cb + PH_AB + (r0 + g) * PHSTR + kk + 2 * t];
                aB[mi][1] = *(const uint32_t*)&sph[cb + PH_AB + (r0 + g + 8) * PHSTR + kk + 2 * t];
                aB[mi][2] = *(const uint32_t*)&sph[cb + PH_AB + (r0 + g) * PHSTR + kk + 2 * t + 8];
                aB[mi][3] = *(const uint32_t*)&sph[cb + PH_AB + (r0 + g + 8) * PHSTR + kk + 2 * t + 8];
                aS[mi][0] = *(const uint32_t*)&sph[cb + PH_AS + (r0 + g) * PHSTR + kk + 2 * t];
                aS[mi][1] = *(const uint32_t*)&sph[cb + PH_AS + (r0 + g + 8) * PHSTR + kk + 2 * t];
                aS[mi][2] = *(const uint32_t*)&sph[cb + PH_AS + (r0 + g) * PHSTR + kk + 2 * t + 8];
                aS[mi][3] = *(const uint32_t*)&sph[cb + PH_AS + (r0 + g + 8) * PHSTR + kk + 2 * t + 8];
            }
            #pragma unroll
            for (int ni = 0; ni < 4; ni++) {
                int c0 = wx * 32 + ni * 8;
                bB[ni][0] = *(const uint32_t*)&sph[cb + PH_WB + (c0 + g) * PHSTR + kk + 2 * t];
                bB[ni][1] = *(const uint32_t*)&sph[cb + PH_WB + (c0 + g) * PHSTR + kk + 2 * t + 8];
                bS[ni][0] = *(const uint32_t*)&sph[cb + PH_WS + (c0 + g) * PHSTR + kk + 2 * t];
                bS[ni][1] = *(const uint32_t*)&sph[cb + PH_WS + (c0 + g) * PHSTR + kk + 2 * t + 8];
            }
            #pragma unroll
            for (int mi = 0; mi < 2; mi++)
                #pragma unroll
                for (int ni = 0; ni < 4; ni++) {
                    mma_f16(acc[mi][ni], aB[mi], bS[ni]);
                    mma_f16(acc[mi][ni], aS[mi], bB[ni]);
                    mma_f16(acc[mi][ni], aB[mi], bB[ni]);
                }
        }
        __syncthreads();
    }
    #pragma unroll
    for (int mi = 0; mi < 2; mi++) {
        int r1 = m0 + wy * 32 + mi * 16 + g;
        int r2 = r1 + 8;
        #pragma unroll
        for (int ni = 0; ni < 4; ni++) {
            int cx = wx * 32 + ni * 8 + 2 * t;
            float b0 = bias ? bias[n0 + cx] : 0.f;
            float b1 = bias ? bias[n0 + cx + 1] : 0.f;
            if (r1 < M)
                *(float2*)&C[(long long)r1 * 256 + n0 + cx] =
                    make_float2(acc[mi][ni][0] + b0, acc[mi][ni][1] + b1);
            if (r2 < M)
                *(float2*)&C[(long long)r2 * 256 + n0 + cx] =
                    make_float2(acc[mi][ni][2] + b0, acc[mi][ni][3] + b1);
        }
    }
}

// ==== scores: fp16 MMA, banded G, coalesced ews out, 2 m-tiles per CTA ======
#define HSTR 40
#define QUH_O 0
#define KTH_O 5120
#define QVH_O 10240
#define PDH_O 15400
#define G_O   12832
#define GSTR  260
#define EH_O  (G_O * 2)
#define ESTR  136
#define SMAX_O (G_O + 128 * GSTR)
#define SSUM_O (SMAX_O + 512)
#define SC_FLOATS (SSUM_O + 512)
#define SC_SMEM (SC_FLOATS * 4)

__global__ __launch_bounds__(256, 1) void scores_mma_kernel(
    const float* __restrict__ q, const float* __restrict__ kmat,
    const float* __restrict__ p, const float* __restrict__ pbu,
    const float* __restrict__ pbv, __half* __restrict__ ews,
    float2* __restrict__ gstats)
{
    extern __shared__ float sm[];
    __half* smh = (__half*)sm;
    int q0 = blockIdx.x * 128;
    int bh = blockIdx.z;
    int b = bh >> 3, h = bh & 7;
    int tid = threadIdx.x;
    int wid = tid >> 5, lane = tid & 31;
    int wy = wid >> 2, wx = wid & 3;
    int g = lane >> 2, t = lane & 3;

    const float* qb = q + (long long)b * KTQ * 256 + h * 32;
    // stage QU once per CTA
    #pragma unroll
    for (int it = 0; it < 4; it++) {
        int e = tid + 256 * it;
        int r = e >> 3, fj = e & 7;
        float4 bu4 = *(const float4*)&pbu[h * 32 + fj * 4];
        float4 a = *(const float4*)&qb[(long long)(q0 + r) * 256 + fj * 4];
        a.x += bu4.x; a.y += bu4.y; a.z += bu4.z; a.w += bu4.w;
        *(uint2*)&smh[QUH_O + r * HSTR + fj * 4] = f4_to_h4(a);
    }
    int da_cur = -100000;

    for (int mt = 0; mt < 2; mt++) {
        int m0 = (blockIdx.y * 2 + mt) * 128;
        int dlo = m0 - q0 + 3969;
        int da  = dlo >> 11;
        bool boundary = (da != ((dlo + 254) >> 11));

        __syncthreads();   // protect KT/PD/QV/G/E reuse across tiles

        if (da != da_cur) {
            da_cur = da;
            #pragma unroll
            for (int it = 0; it < 5; it++) {
                int e = tid + 256 * it;
                if (e < 129 * 8) {
                    int r = e >> 3, fj = e & 7;
                    float4 bv4 = *(const float4*)&pbv[h * 32 + fj * 4];
                    int rv = q0 + da + r; if (rv > KTQ - 1) rv = KTQ - 1;
                    float4 v = *(const float4*)&qb[(long long)rv * 256 + fj * 4];
                    v.x += bv4.x; v.y += bv4.y; v.z += bv4.z; v.w += bv4.w;
                    *(uint2*)&smh[QVH_O + r * HSTR + fj * 4] = f4_to_h4(v);
                }
            }
        }
        #pragma unroll
        for (int it = 0; it < 4; it++) {
            int e = tid + 256 * it;
            int r = e >> 3, fj = e & 7;
            float4 kk4 = *(const float4*)&kmat[(long long)(m0 + r) * 256 + h * 32 + fj * 4];
            *(uint2*)&smh[KTH_O + r * HSTR + fj * 4] = f4_to_h4(kk4);
        }
        #pragma unroll
        for (int it = 0; it < 8; it++) {
            int e = tid + 256 * it;
            int r = e >> 3, fj = e & 7;
            int d = dlo + r;
            int cm = d & 2047;
            float4 v = make_float4(0.f, 0.f, 0.f, 0.f);
            if (cm > 0 && r < 255)
                v = *(const float4*)&p[(long long)(cm - 1) * 256 + h * 32 + fj * 4];
            *(uint2*)&smh[PDH_O + r * HSTR + fj * 4] = f4_to_h4(v);
        }
        __syncthreads();

        // ---- phase 1: banded G ----
        if (!boundary) {
            int s0b = (wy == 0) ? 64 : 0;
            float accg[4][6][4] = {};
            #pragma unroll
            for (int k0 = 0; k0 < 2; k0++) {
                int kk = k0 * 16;
                uint32_t a[4][4], bb[6][2];
                #pragma unroll
                for (int mi = 0; mi < 4; mi++) {
                    int r0 = wy * 64 + mi * 16;
                    a[mi][0] = *(const uint32_t*)&smh[QVH_O + (r0 + g) * HSTR + kk + 2 * t];
                    a[mi][1] = *(const uint32_t*)&smh[QVH_O + (r0 + g + 8) * HSTR + kk + 2 * t];
                    a[mi][2] = *(const uint32_t*)&smh[QVH_O + (r0 + g) * HSTR + kk + 2 * t + 8];
                    a[mi][3] = *(const uint32_t*)&smh[QVH_O + (r0 + g + 8) * HSTR + kk + 2 * t + 8];
                }
                #pragma unroll
                for (int ni = 0; ni < 6; ni++) {
                    int c0 = s0b + (wx * 6 + ni) * 8;
                    bb[ni][0] = *(const uint32_t*)&smh[PDH_O + (c0 + g) * HSTR + kk + 2 * t];
                    bb[ni][1] = *(const uint32_t*)&smh[PDH_O + (c0 + g) * HSTR + kk + 2 * t + 8];
                }
                #pragma unroll
                for (int mi = 0; mi < 4; mi++)
                    #pragma unroll
                    for (int ni = 0; ni < 6; ni++)
                        mma_f16(accg[mi][ni], a[mi], bb[ni]);
            }
            #pragma unroll
            for (int mi = 0; mi < 4; mi++) {
                int r1 = wy * 64 + mi * 16 + g;
                #pragma unroll
                for (int ni = 0; ni < 6; ni++) {
                    int cx = s0b + (wx * 6 + ni) * 8 + 2 * t;
                    *(float2*)&sm[G_O + r1 * GSTR + cx] =
                        make_float2(accg[mi][ni][0], accg[mi][ni][1]);
                    *(float2*)&sm[G_O + (r1 + 8) * GSTR + cx] =
                        make_float2(accg[mi][ni][2], accg[mi][ni][3]);
                }
            }
        } else {
            int trb = (tid >> 4) * 8, tcb = (tid & 15) * 8;
            #pragma unroll
            for (int i = 0; i < 8; i++) {
                int rr = trb + i;
                #pragma unroll
                for (int j = 0; j < 8; j++) {
                    int c = tcb + j;
                    int ix = c - rr + 127;
                    int d = dlo + ix;
                    int tt = rr + (d >> 11) - da;
                    float s = 0.f;
                    #pragma unroll
                    for (int k = 0; k < 32; k++)
                        s += __half2float(smh[QVH_O + tt * HSTR + k])
                           * __half2float(smh[PDH_O + ix * HSTR + k]);
                    sm[G_O + rr * GSTR + ix] = s;
                }
            }
        }
        __syncthreads();

        // ---- phase 2: ac = Qu . K^T ----
        float acc[4][4][4] = {};
        #pragma unroll
        for (int k0 = 0; k0 < 2; k0++) {
            int kk = k0 * 16;
            uint32_t a[4][4], bb[4][2];
            #pragma unroll
            for (int mi = 0; mi < 4; mi++) {
                int r0 = wy * 64 + mi * 16;
                a[mi][0] = *(const uint32_t*)&smh[QUH_O + (r0 + g) * HSTR + kk + 2 * t];
                a[mi][1] = *(const uint32_t*)&smh[QUH_O + (r0 + g + 8) * HSTR + kk + 2 * t];
                a[mi][2] = *(const uint32_t*)&smh[QUH_O + (r0 + g) * HSTR + kk + 2 * t + 8];
                a[mi][3] = *(const uint32_t*)&smh[QUH_O + (r0 + g + 8) * HSTR + kk + 2 * t + 8];
            }
            #pragma unroll
            for (int ni = 0; ni < 4; ni++) {
                int c0 = wx * 32 + ni * 8;
                bb[ni][0] = *(const uint32_t*)&smh[KTH_O + (c0 + g) * HSTR + kk + 2 * t];
                bb[ni][1] = *(const uint32_t*)&smh[KTH_O + (c0 + g) * HSTR + kk + 2 * t + 8];
            }
            #pragma unroll
            for (int mi = 0; mi < 4; mi++)
                #pragma unroll
                for (int ni = 0; ni < 4; ni++)
                    mma_f16(acc[mi][ni], a[mi], bb[ni]);
        }

        // ---- combine with bd, scale ----
        const float sc = 0.17677669529663687f;
        #pragma unroll
        for (int mi = 0; mi < 4; mi++) {
            int r1 = wy * 64 + mi * 16 + g;
            int r2 = r1 + 8;
            #pragma unroll
            for (int ni = 0; ni < 4; ni++) {
                int cx = wx * 32 + ni * 8 + 2 * t;
                acc[mi][ni][0] = (acc[mi][ni][0] + sm[G_O + r1 * GSTR + cx     - r1 + 127]) * sc;
                acc[mi][ni][1] = (acc[mi][ni][1] + sm[G_O + r1 * GSTR + cx + 1 - r1 + 127]) * sc;
                acc[mi][ni][2] = (acc[mi][ni][2] + sm[G_O + r2 * GSTR + cx     - r2 + 127]) * sc;
                acc[mi][ni][3] = (acc[mi][ni][3] + sm[G_O + r2 * GSTR + cx + 1 - r2 + 127]) * sc;
            }
        }

        // ---- row-tile max reduce ----
        __syncthreads();
        float rm1[4], rm2[4];
        #pragma unroll
        for (int mi = 0; mi < 4; mi++) {
            int lr1 = wy * 64 + mi * 16 + g;
            int lr2 = lr1 + 8;
            float mx1 = -1e30f, mx2 = -1e30f;
            #pragma unroll
            for (int ni = 0; ni < 4; ni++) {
                mx1 = fmaxf(mx1, fmaxf(acc[mi][ni][0], acc[mi][ni][1]));
                mx2 = fmaxf(mx2, fmaxf(acc[mi][ni][2], acc[mi][ni][3]));
            }
            mx1 = fmaxf(mx1, __shfl_xor_sync(0xffffffffu, mx1, 1));
            mx1 = fmaxf(mx1, __shfl_xor_sync(0xffffffffu, mx1, 2));
            mx2 = fmaxf(mx2, __shfl_xor_sync(0xffffffffu, mx2, 1));
            mx2 = fmaxf(mx2, __shfl_xor_sync(0xffffffffu, mx2, 2));
            if (t == 0) {
                sm[SMAX_O + lr1 * 4 + wx] = mx1;
                sm[SMAX_O + lr2 * 4 + wx] = mx2;
            }
        }
        __syncthreads();

        // ---- exp + stage E + sum reduce ----
        #pragma unroll
        for (int mi = 0; mi < 4; mi++) {
            int lr1 = wy * 64 + mi * 16 + g;
            int lr2 = lr1 + 8;
            float a1 = fmaxf(fmaxf(sm[SMAX_O + lr1 * 4], sm[SMAX_O + lr1 * 4 + 1]),
                             fmaxf(sm[SMAX_O + lr1 * 4 + 2], sm[SMAX_O + lr1 * 4 + 3]));
            float a2 = fmaxf(fmaxf(sm[SMAX_O + lr2 * 4], sm[SMAX_O + lr2 * 4 + 1]),
                             fmaxf(sm[SMAX_O + lr2 * 4 + 2], sm[SMAX_O + lr2 * 4 + 3]));
            rm1[mi] = a1; rm2[mi] = a2;
            float s1 = 0.f, s2 = 0.f;
            #pragma unroll
            for (int ni = 0; ni < 4; ni++) {
                int cx = wx * 32 + ni * 8 + 2 * t;
                float e0 = __expf(acc[mi][ni][0] - a1);
                float e1 = __expf(acc[mi][ni][1] - a1);
                float e2 = __expf(acc[mi][ni][2] - a2);
                float e3 = __expf(acc[mi][ni][3] - a2);
                s1 += e0 + e1;
                s2 += e2 + e3;
                __half2 h0 = __floats2half2_rn(e0, e1);
                __half2 h1 = __floats2half2_rn(e2, e3);
                *(uint32_t*)&smh[EH_O + lr1 * ESTR + cx] = *reinterpret_cast<uint32_t*>(&h0);
                *(uint32_t*)&smh[EH_O + lr2 * ESTR + cx] = *reinterpret_cast<uint32_t*>(&h1);
            }
            s1 += __shfl_xor_sync(0xffffffffu, s1, 1);
            s1 += __shfl_xor_sync(0xffffffffu, s1, 2);
            s2 += __shfl_xor_sync(0xffffffffu, s2, 1);
            s2 += __shfl_xor_sync(0xffffffffu, s2, 2);
            if (t == 0) {
                sm[SSUM_O + lr1 * 4 + wx] = s1;
                sm[SSUM_O + lr2 * 4 + wx] = s2;
            }
        }
        __syncthreads();

        // ---- coalesced ews store + stats ----
        {
            long long gbase = ((long long)bh * KTQ + q0) * KS + m0;
            #pragma unroll
            for (int it = 0; it < 8; it++) {
                int e = tid + 256 * it;
                int r = e >> 4, f = e & 15;
                uint4 v = *(const uint4*)&smh[EH_O + r * ESTR + f * 8];
                *(uint4*)&ews[gbase + (long long)r * KS + f * 8] = v;
            }
        }
        if (wx == 0 && t == 0) {
            int my = m0 >> 7;
            long long sb = ((long long)bh * 8 + my) * KTQ + q0;
            #pragma unroll
            for (int mi = 0; mi < 4; mi++) {
                int lr1 = wy * 64 + mi * 16 + g;
                int lr2 = lr1 + 8;
                float s1 = sm[SSUM_O + lr1 * 4] + sm[SSUM_O + lr1 * 4 + 1]
                         + sm[SSUM_O + lr1 * 4 + 2] + sm[SSUM_O + lr1 * 4 + 3];
                float s2 = sm[SSUM_O + lr2 * 4] + sm[SSUM_O + lr2 * 4 + 1]
                         + sm[SSUM_O + lr2 * 4 + 2] + sm[SSUM_O + lr2 * 4 + 3];
                gstats[sb + lr1] = make_float2(rm1[mi], s1);
                gstats[sb + lr2] = make_float2(rm2[mi], s2);
            }
        }
    }
}

// ===== av: raw fp16 e as A operand, fp16 V as B, fac folded in epilogue =====
#define AHSTR 72
#define AVH_A 0
#define AVH_V (128 * AHSTR)
#define AV_M 5760
#define AV_I 5888
#define AV_S 6016
#define AV_F 8064
#define AV_SMEM ((8064 + 1024) * 4)

__global__ __launch_bounds__(256) void av_fused(
    const __half* __restrict__ ews, float* __restrict__ ws,
    const float* __restrict__ vmat,
    const float2* __restrict__ gstats, float* __restrict__ ao)
{
    extern __shared__ float sv[];
    __half* svh = (__half*)sv;
    float2* sSt = (float2*)(sv + AV_S);
    int q0 = blockIdx.x * 128;
    int bh = blockIdx.y;
    int b = bh >> 3, h = bh & 7;
    int tid = threadIdx.x;
    int wid = tid >> 5, lane = tid & 31;
    int g = lane >> 2, t = lane & 3;

    for (int idx = tid; idx < 1024; idx += 256)
        sSt[idx] = gstats[(((long long)bh * 8 + (idx >> 7)) << 12) + q0 + (idx & 127)];
    __syncthreads();
    if (tid < 128) {
        float M = -1e30f;
        #pragma unroll
        for (int mt = 0; mt < 8; mt++) M = fmaxf(M, sSt[mt * 128 + tid].x);
        float s = 0.f;
        #pragma unroll
        for (int mt = 0; mt < 8; mt++)
            s += sSt[mt * 128 + tid].y * __expf(sSt[mt * 128 + tid].x - M);
        sv[AV_M + tid] = M;
        sv[AV_I + tid] = 1.f / s;
    }
    __syncthreads();
    for (int idx = tid; idx < 1024; idx += 256) {
        int r = idx & 127;
        sv[AV_F + idx] = __expf(sSt[idx].x - sv[AV_M + r]) * sv[AV_I + r];
    }
    __syncthreads();

    const __half* ewsrow = ews + ((long long)bh * KTQ + q0) * KS;
    float* wsrow = ws + ((long long)bh * KTQ + q0) * KS;
    float acc[4][4] = {};

    for (int s0 = 0; s0 < KS; s0 += 64) {
        int mt = s0 >> 7;
        #pragma unroll
        for (int it = 0; it < 4; it++) {
            int e = tid + 256 * it;
            int r = e >> 3, f = e & 7;
            long long off = (long long)r * KS + s0 + f * 8;
            uint4 rh = *(const uint4*)&ewsrow[off];
            *(uint4*)&svh[AVH_A + r * AHSTR + f * 8] = rh;
            float fac = sv[AV_F + mt * 128 + r];
            float2 p0 = __half22float2(*reinterpret_cast<__half2*>(&rh.x));
            float2 p1 = __half22float2(*reinterpret_cast<__half2*>(&rh.y));
            float2 p2 = __half22float2(*reinterpret_cast<__half2*>(&rh.z));
            float2 p3 = __half22float2(*reinterpret_cast<__half2*>(&rh.w));
            float4 o0 = make_float4(p0.x * fac, p0.y * fac, p1.x * fac, p1.y * fac);
            float4 o1 = make_float4(p2.x * fac, p2.y * fac, p3.x * fac, p3.y * fac);
            *(float4*)&wsrow[off]     = o0;
            *(float4*)&wsrow[off + 4] = o1;
        }
        #pragma unroll
        for (int it = 0; it < 8; it++) {
            int e = tid + 256 * it;
            int k = e >> 5, n = e & 31;
            svh[AVH_V + n * AHSTR + k] =
                __float2half_rn(vmat[(long long)(s0 + k) * 256 + h * 32 + n]);
        }
        __syncthreads();

        int r0 = wid * 16;
        float accC[4][4] = {};
        #pragma unroll
        for (int k0 = 0; k0 < 4; k0++) {
            int kk = k0 * 16;
            uint32_t a[4];
            a[0] = *(const uint32_t*)&svh[AVH_A + (r0 + g) * AHSTR + kk + 2 * t];
            a[1] = *(const uint32_t*)&svh[AVH_A + (r0 + g + 8) * AHSTR + kk + 2 * t];
            a[2] = *(const uint32_t*)&svh[AVH_A + (r0 + g) * AHSTR + kk + 2 * t + 8];
            a[3] = *(const uint32_t*)&svh[AVH_A + (r0 + g + 8) * AHSTR + kk + 2 * t + 8];
            #pragma unroll
            for (int ni = 0; ni < 4; ni++) {
                uint32_t bb[2];
                bb[0] = *(const uint32_t*)&svh[AVH_V + (ni * 8 + g) * AHSTR + kk + 2 * t];
                bb[1] = *(const uint32_t*)&svh[AVH_V + (ni * 8 + g) * AHSTR + kk + 2 * t + 8];
                mma_f16(accC[ni], a, bb);
            }
        }
        float facA = sv[AV_F + mt * 128 + r0 + g];
        float facB = sv[AV_F + mt * 128 + r0 + g + 8];
        #pragma unroll
        for (int ni = 0; ni < 4; ni++) {
            acc[ni][0] += facA * accC[ni][0];
            acc[ni][1] += facA * accC[ni][1];
            acc[ni][2] += facB * accC[ni][2];
            acc[ni][3] += facB * accC[ni][3];
        }
        __syncthreads();
    }
    int r1 = q0 + wid * 16 + g;
    float* aob = ao + ((long long)b * KTQ + r1) * 256 + h * 32;
    #pragma unroll
    for (int ni = 0; ni < 4; ni++) {
        int cx = ni * 8 + 2 * t;
        *(float2*)&aob[cx]           = make_float2(acc[ni][0], acc[ni][1]);
        *(float2*)&aob[8 * 256 + cx] = make_float2(acc[ni][2], acc[ni][3]);
    }
}

// ---------------------------------------------------------------------------
extern "C" void kernel_launch(void* const* d_in, const int* in_sizes, int n_in,
                              void* d_out, int out_size)
{
    const float* vis  = (const float*)d_in[0];
    const float* mem  = (const float*)d_in[1];
    const float* Wq   = (const float*)d_in[3];
    const float* bq   = (const float*)d_in[4];
    const float* Wk   = (const float*)d_in[5];
    const float* bk   = (const float*)d_in[6];
    const float* Wv   = (const float*)d_in[7];
    const float* bv   = (const float*)d_in[8];
    const float* Wo   = (const float*)d_in[9];
    const float* bo   = (const float*)d_in[10];
    const float* Wpos = (const float*)d_in[11];
    const float* pbu  = (const float*)d_in[12];
    const float* pbv  = (const float*)d_in[13];

    float* out    = (float*)d_out;
    float* out_ws = out + XE;

    float* scratch = nullptr;
    cudaGetSymbolAddress((void**)&scratch, g_scratch);
    __half* ews = nullptr;
    cudaGetSymbolAddress((void**)&ews, g_ews);
    float* pe = scratch;
    float* pp = pe + 524032;
    float* kk = pp + 4 * 524032;
    float* vv = kk + 4 * 262144;
    float* qq = vv + 4 * 262144;
    float* xx = qq + XE;
    float* ao = xx + XE;
    float2* gstats = (float2*)(ao + XE);

    cudaFuncSetAttribute(scores_mma_kernel,
        cudaFuncAttributeMaxDynamicSharedMemorySize, SC_SMEM);
    cudaFuncSetAttribute(proj_mma,
        cudaFuncAttributeMaxDynamicSharedMemorySize, PJ_SMEM);
    cudaFuncSetAttribute(av_fused,
        cudaFuncAttributeMaxDynamicSharedMemorySize, AV_SMEM);

    pe_kernel<<<KP, 128>>>(pe);

    proj_mma<<<dim3(8, 2, 2 * KL), 512, PJ_SMEM>>>(mem, Wk, bk, kk, KS, 65536, 262144,
                                                   Wv, bv, vv, KL);
    proj_mma<<<dim3(16, 2, KL), 512, PJ_SMEM>>>(pe, Wpos, nullptr, pp, KP, 65536, 524032,
                                                nullptr, nullptr, nullptr, 1 << 30);

    const float* cur = vis;
    for (int l = 0; l < KL; l++) {
        proj_mma<<<dim3(64, 2, 1), 512, PJ_SMEM>>>(cur, Wq + l * 65536, bq + l * 256,
                                                   qq, KB * KTQ, 0, 0,
                                                   nullptr, nullptr, nullptr, 1 << 30);
        float* wsl = out_ws + (long long)l * KB * KH * KTQ * KS;
        scores_mma_kernel<<<dim3(32, 4, 16), 256, SC_SMEM>>>(
            qq, kk + l * 262144, pp + l * 524032,
            pbu + l * 256, pbv + l * 256, ews, gstats);
        av_fused<<<dim3(32, 16), 256, AV_SMEM>>>(ews, wsl, vv + l * 262144, gstats, ao);
        float* nxt = (l == KL - 1) ? out : xx;
        proj_mma<<<dim3(64, 2, 1), 512, PJ_SMEM>>>(ao, Wo + l * 65536, bo + l * 256,
                                                   nxt, KB * KTQ, 0, 0,
                                                   nullptr, nullptr, nullptr, 1 << 30);
        cur = nxt;
    }
}